// round 5
// baseline (speedup 1.0000x reference)
#include <cuda_runtime.h>
#include <cuda_bf16.h>
#include <math.h>
#include <stdint.h>

#define BB 1024
#define NN 128
#define KK 4
#define MTOT (BB*NN)     // 131072
#define ME  (MTOT*KK)    // 524288 edges
#define KP1 480          // hcat padded K (head GEMM1)
#define KP2 512          // head GEMM2 K (= GEMM1 N padded)

// ---------------- scratch (device globals: allocation-free) ----------------
__device__ float g_out1[MTOT*64];
__device__ float g_out2[MTOT*128];
__device__ float g_U[MTOT*96];
__device__ float g_V[MTOT*96];
__device__ float g_UV[(size_t)MTOT*384];     // stage1-ec3 out: [U(192)|V(192)]
__device__ int   g_idx[MTOT*KK];
__device__ float g_h2[(size_t)MTOT*256];
__device__ float g_b1p[512];
__device__ float g_b2p[256];
__device__ float g_W3p[256*2];
__device__ float g_sb1[384];

// bf16 split operands (16B aligned)
// hcat layout (cols): [0..5)=feats [5..8)=0 [8..72)=out1 [72..200)=out2 [200..456)=out3 [456..480)=0
__device__ __align__(16) __nv_bfloat16 g_A1h[(size_t)MTOT*KP1];
__device__ __align__(16) __nv_bfloat16 g_A1l[(size_t)MTOT*KP1];
__device__ __align__(16) __nv_bfloat16 g_h1h[(size_t)MTOT*KP2];
__device__ __align__(16) __nv_bfloat16 g_h1l[(size_t)MTOT*KP2];
__device__ __align__(16) __nv_bfloat16 g_Bt1h[512*KP1];
__device__ __align__(16) __nv_bfloat16 g_Bt1l[512*KP1];
__device__ __align__(16) __nv_bfloat16 g_Bt2h[256*KP2];
__device__ __align__(16) __nv_bfloat16 g_Bt2l[256*KP2];
__device__ __align__(16) __nv_bfloat16 g_Bc2h[128*96];
__device__ __align__(16) __nv_bfloat16 g_Bc2l[128*96];
__device__ __align__(16) __nv_bfloat16 g_Bc3h[256*192];
__device__ __align__(16) __nv_bfloat16 g_Bc3l[256*192];
__device__ __align__(16) __nv_bfloat16 g_Bs1h[384*128];
__device__ __align__(16) __nv_bfloat16 g_Bs1l[384*128];

__device__ __forceinline__ float eluf(float x) { return x > 0.f ? x : expm1f(x); }

__device__ __forceinline__ uint32_t smem_u32(const void* p) {
    uint32_t a;
    asm("{ .reg .u64 t; cvta.to.shared.u64 t, %1; cvt.u32.u64 %0, t; }" : "=r"(a) : "l"(p));
    return a;
}
__device__ __forceinline__ void cp16(uint32_t dst, const void* src) {
    asm volatile("cp.async.cg.shared.global [%0], [%1], 16;" :: "r"(dst), "l"(src));
}
#define CP_COMMIT() asm volatile("cp.async.commit_group;" ::: "memory")
#define CP_WAIT(n)  asm volatile("cp.async.wait_group %0;" :: "n"(n) : "memory")

#define LDSM_X4(r0, r1, r2, r3, addr) \
    asm volatile("ldmatrix.sync.aligned.m8n8.x4.shared.b16 {%0,%1,%2,%3}, [%4];" \
        : "=r"(r0), "=r"(r1), "=r"(r2), "=r"(r3) : "r"(addr))
#define LDSM_X2(r0, r1, addr) \
    asm volatile("ldmatrix.sync.aligned.m8n8.x2.shared.b16 {%0,%1}, [%2];" \
        : "=r"(r0), "=r"(r1) : "r"(addr))

#define MMA16816(d, a0, a1, a2, a3, b0, b1) \
    asm volatile("mma.sync.aligned.m16n8k16.row.col.f32.bf16.bf16.f32 " \
        "{%0,%1,%2,%3}, {%4,%5,%6,%7}, {%8,%9}, {%0,%1,%2,%3};" \
        : "+f"((d)[0]), "+f"((d)[1]), "+f"((d)[2]), "+f"((d)[3]) \
        : "r"(a0), "r"(a1), "r"(a2), "r"(a3), "r"(b0), "r"(b1))

#define STG_BYTES 40960
#define ROWB 80

// ---------------- weight prep ----------------
__global__ void pad_copy_kernel(float* __restrict__ dst, const float* __restrict__ src,
                                int sr, int sc, int dr, int dc) {
    int tot = dr * dc;
    for (int i = blockIdx.x * blockDim.x + threadIdx.x; i < tot; i += gridDim.x * blockDim.x) {
        int r = i / dc, c = i % dc;
        dst[i] = (r < sr && c < sc) ? src[r * sc + c] : 0.f;
    }
}

// split fp32 weight [sr x sc] -> transposed bf16 hi/lo [Np x Kp]
__global__ void split_w_kernel(const float* __restrict__ W, int sr, int sc,
                               __nv_bfloat16* __restrict__ oh, __nv_bfloat16* __restrict__ ol,
                               int Np, int Kp) {
    int tot = Np * Kp;
    for (int i = blockIdx.x * blockDim.x + threadIdx.x; i < tot; i += gridDim.x * blockDim.x) {
        int n = i / Kp, k = i % Kp;
        float v = (k < sr && n < sc) ? W[k * sc + n] : 0.f;
        __nv_bfloat16 h = __float2bfloat16(v);
        oh[i] = h;
        ol[i] = __float2bfloat16(v - __bfloat162float(h));
    }
}

// head GEMM1 weight with hcat-permuted K rows: [512][KP1]
__global__ void split_w1p_kernel(const float* __restrict__ W,
                                 __nv_bfloat16* __restrict__ oh, __nv_bfloat16* __restrict__ ol) {
    int tot = 512 * KP1;
    for (int i = blockIdx.x * blockDim.x + threadIdx.x; i < tot; i += gridDim.x * blockDim.x) {
        int n = i / KP1, k = i % KP1;
        int src = -1;
        if (k < 5)                   src = k;
        else if (k >= 8 && k < 72)   src = 5 + (k - 8);
        else if (k >= 72 && k < 200) src = 69 + (k - 72);
        else if (k >= 200 && k < 456) src = 197 + (k - 200);
        float v = (src >= 0 && n < 453) ? W[(size_t)src * 453 + n] : 0.f;
        __nv_bfloat16 h = __float2bfloat16(v);
        oh[i] = h;
        ol[i] = __float2bfloat16(v - __bfloat162float(h));
    }
}

// stage1-ec3 combined weight: rows 0..191 = W1b^T, 192..383 = (W1a-W1b)^T; bias [0|b1]
__global__ void split_s1w_kernel(const float* __restrict__ w1, const float* __restrict__ b1,
                                 __nv_bfloat16* __restrict__ oh, __nv_bfloat16* __restrict__ ol,
                                 float* __restrict__ biasv) {
    int tot = 384 * 128;
    int t0 = blockIdx.x * blockDim.x + threadIdx.x;
    for (int i = t0; i < tot; i += gridDim.x * blockDim.x) {
        int n = i >> 7, k = i & 127;
        float v;
        if (n < 192) v = w1[(size_t)(128 + k) * 192 + n];
        else         v = w1[(size_t)k * 192 + (n - 192)] - w1[(size_t)(128 + k) * 192 + (n - 192)];
        __nv_bfloat16 h = __float2bfloat16(v);
        oh[i] = h;
        ol[i] = __float2bfloat16(v - __bfloat162float(h));
    }
    if (t0 < 384) biasv[t0] = (t0 < 192) ? 0.f : b1[t0 - 192];
}

// fill hcat edge cols: 0..8 (feats+pad) and 456..480 (pad)
__global__ void hcat_edges_kernel(const float* __restrict__ feats) {
    size_t total = (size_t)MTOT * 32;
    for (size_t i = (size_t)blockIdx.x * blockDim.x + threadIdx.x; i < total;
         i += (size_t)gridDim.x * blockDim.x) {
        size_t m = i >> 5;
        int cq = (int)(i & 31);
        int c = (cq < 8) ? cq : 448 + cq;
        float v = (c < 5) ? feats[m * 5 + c] : 0.f;
        __nv_bfloat16 h = __float2bfloat16(v);
        g_A1h[m * KP1 + c] = h;
        g_A1l[m * KP1 + c] = __float2bfloat16(v - __bfloat162float(h));
    }
}

// ================= bf16x3-split tensor-core GEMM (mma.sync) =================
// out = post(A[M x Kdim(lda)] @ B^T[N x Kdim] + bias), via ah*bh + ah*bl + al*bh.
// CTA tile 128x128, 8 warps (2Mx4N), warp tile 64x32, cp.async double buffer.
// mode 0: elu + bf16-split (oh/ol, ldo). mode 1: elu + fp32 (of). mode 3: plain fp32 (of).
__global__ void __launch_bounds__(256) gemm_mma(
    const __nv_bfloat16* __restrict__ Ah, const __nv_bfloat16* __restrict__ Al, int lda,
    const __nv_bfloat16* __restrict__ Bh, const __nv_bfloat16* __restrict__ Bl,
    const float* __restrict__ bias,
    __nv_bfloat16* __restrict__ oh, __nv_bfloat16* __restrict__ ol,
    float* __restrict__ of, int ldo, int Kdim, int mode) {
    extern __shared__ char smem[];
    float* sbias = (float*)(smem + 2 * STG_BYTES);

    const int tid = threadIdx.x;
    const int warp = tid >> 5, lane = tid & 31;
    const size_t m0 = (size_t)blockIdx.x * 128;
    const int n0 = blockIdx.y * 128;
    const uint32_t sb = smem_u32(smem);

    if (tid < 128) sbias[tid] = bias[n0 + tid];

    auto issue = [&](int st, int k0) {
        uint32_t base = sb + st * STG_BYTES;
        #pragma unroll
        for (int i = tid; i < 2048; i += 256) {
            int mat = i >> 9, j = i & 511, r = j >> 2, c = j & 3;
            uint32_t daddr = base + mat * 10240 + r * ROWB + c * 16;
            const __nv_bfloat16* g;
            if (mat == 0)      g = &Ah[(m0 + r) * lda + k0 + c * 8];
            else if (mat == 1) g = &Al[(m0 + r) * lda + k0 + c * 8];
            else if (mat == 2) g = &Bh[(size_t)(n0 + r) * Kdim + k0 + c * 8];
            else               g = &Bl[(size_t)(n0 + r) * Kdim + k0 + c * 8];
            cp16(daddr, g);
        }
        CP_COMMIT();
    };

    const int wm = warp & 1, wn = warp >> 1;
    const int mbase = wm * 64, nbase = wn * 32;

    float acc[4][4][4];
    #pragma unroll
    for (int mi = 0; mi < 4; mi++)
        #pragma unroll
        for (int ni = 0; ni < 4; ni++)
            #pragma unroll
            for (int q = 0; q < 4; q++) acc[mi][ni][q] = 0.f;

    const int lr = lane & 7, seg = lane >> 3;
    const int arow = mbase + (seg & 1) * 8 + lr;
    const int acolq = (seg >> 1) * 8;
    const int brow = nbase + lr;
    const int bcolq = (seg & 1) * 8;

    issue(0, 0);

    const int NSTEP = Kdim >> 5;
    #pragma unroll 1
    for (int s = 0; s < NSTEP; s++) {
        if (s + 1 < NSTEP) { issue((s + 1) & 1, (s + 1) * 32); CP_WAIT(1); }
        else               { CP_WAIT(0); }
        __syncthreads();
        uint32_t base = sb + (s & 1) * STG_BYTES;
        uint32_t bAh = base, bAl = base + 10240, bBh = base + 20480, bBl = base + 30720;

        #pragma unroll
        for (int ks = 0; ks < 2; ks++) {
            int acol = ks * 16 + acolq;
            int bcol = ks * 16 + bcolq;
            uint32_t ah[4][4], al_[4][4], bh[4][2], bl[4][2];
            #pragma unroll
            for (int mi = 0; mi < 4; mi++) {
                LDSM_X4(ah[mi][0], ah[mi][1], ah[mi][2], ah[mi][3],
                        bAh + (arow + mi * 16) * ROWB + acol * 2);
                LDSM_X4(al_[mi][0], al_[mi][1], al_[mi][2], al_[mi][3],
                        bAl + (arow + mi * 16) * ROWB + acol * 2);
            }
            #pragma unroll
            for (int ni = 0; ni < 4; ni++) {
                LDSM_X2(bh[ni][0], bh[ni][1], bBh + (brow + ni * 8) * ROWB + bcol * 2);
                LDSM_X2(bl[ni][0], bl[ni][1], bBl + (brow + ni * 8) * ROWB + bcol * 2);
            }
            #pragma unroll
            for (int mi = 0; mi < 4; mi++)
                #pragma unroll
                for (int ni = 0; ni < 4; ni++) {
                    MMA16816(acc[mi][ni], ah[mi][0], ah[mi][1], ah[mi][2], ah[mi][3],
                             bh[ni][0], bh[ni][1]);
                    MMA16816(acc[mi][ni], ah[mi][0], ah[mi][1], ah[mi][2], ah[mi][3],
                             bl[ni][0], bl[ni][1]);
                    MMA16816(acc[mi][ni], al_[mi][0], al_[mi][1], al_[mi][2], al_[mi][3],
                             bh[ni][0], bh[ni][1]);
                }
        }
        __syncthreads();
    }

    const int gq = lane >> 2, tq = lane & 3;
    const bool doelu = (mode != 3);
    #pragma unroll
    for (int mi = 0; mi < 4; mi++) {
        #pragma unroll
        for (int ni = 0; ni < 4; ni++) {
            #pragma unroll
            for (int half = 0; half < 2; half++) {
                size_t m = m0 + mbase + mi * 16 + gq + half * 8;
                int nl = nbase + ni * 8 + tq * 2;
                float v0 = acc[mi][ni][half * 2 + 0] + sbias[nl];
                float v1 = acc[mi][ni][half * 2 + 1] + sbias[nl + 1];
                if (doelu) { v0 = eluf(v0); v1 = eluf(v1); }
                size_t o = m * (size_t)ldo + n0 + nl;
                if (mode == 0) {
                    __nv_bfloat162 hv, lv;
                    hv.x = __float2bfloat16(v0);
                    hv.y = __float2bfloat16(v1);
                    lv.x = __float2bfloat16(v0 - __bfloat162float(hv.x));
                    lv.y = __float2bfloat16(v1 - __bfloat162float(hv.y));
                    *(__nv_bfloat162*)&oh[o] = hv;
                    *(__nv_bfloat162*)&ol[o] = lv;
                } else {
                    *(float2*)&of[o] = make_float2(v0, v1);
                }
            }
        }
    }
}

// ================= fused edge-gather stage-2 GEMM =================
// A rows = 128 edges built on the fly: elu(V[p] + U[idx]) -> bf16 split -> smem.
// Epilogue: bias + elu per edge, mean over 4 edges -> fp32 out (opt) + hcat split.
__global__ void __launch_bounds__(256) gemm_edge(
    const float* __restrict__ Ub, const float* __restrict__ Vb, int suv,
    const int* __restrict__ idx,
    const __nv_bfloat16* __restrict__ Bh, const __nv_bfloat16* __restrict__ Bl,
    const float* __restrict__ bias,
    float* __restrict__ of, int ldof,
    __nv_bfloat16* __restrict__ oh, __nv_bfloat16* __restrict__ ol, int obase,
    int Kdim) {
    extern __shared__ char smem[];
    float* sbias = (float*)(smem + 2 * STG_BYTES);
    int*   sidx  = (int*)(smem + 2 * STG_BYTES + 512);

    const int tid = threadIdx.x;
    const int warp = tid >> 5, lane = tid & 31;
    const size_t m0 = (size_t)blockIdx.x * 128;   // edge base
    const int n0 = blockIdx.y * 128;
    const uint32_t sb = smem_u32(smem);

    if (tid < 128) {
        sbias[tid] = bias[n0 + tid];
        sidx[tid] = idx[m0 + tid];
    }
    __syncthreads();

    // loader thread mapping: 2 threads per edge row, 16 cols each
    const int arw = tid >> 1;
    const int halfc = (tid & 1) * 16;
    const int ep = (int)((m0 + arw) >> 2);              // point of this row
    const float* vrow = Vb + (size_t)ep * suv + halfc;
    const int jrow = (ep & ~127) + sidx[arw];
    const float* urow = Ub + (size_t)jrow * suv + halfc;

    auto issueB = [&](int st, int k0) {
        uint32_t base = sb + st * STG_BYTES;
        #pragma unroll
        for (int i = tid; i < 1024; i += 256) {
            int mat = i >> 9, j = i & 511, r = j >> 2, c = j & 3;
            uint32_t daddr = base + (2 + mat) * 10240 + r * ROWB + c * 16;
            const __nv_bfloat16* g = (mat == 0)
                ? &Bh[(size_t)(n0 + r) * Kdim + k0 + c * 8]
                : &Bl[(size_t)(n0 + r) * Kdim + k0 + c * 8];
            cp16(daddr, g);
        }
        CP_COMMIT();
    };

    float4 rv[4], ru[4];
    auto loadA = [&](int k0) {
        #pragma unroll
        for (int q = 0; q < 4; q++) {
            rv[q] = *(const float4*)(vrow + k0 + q * 4);
            ru[q] = *(const float4*)(urow + k0 + q * 4);
        }
    };
    auto storeA = [&](int st) {
        __nv_bfloat16 hbuf[16], lbuf[16];
        #pragma unroll
        for (int q = 0; q < 4; q++) {
            float vals[4] = {rv[q].x + ru[q].x, rv[q].y + ru[q].y,
                             rv[q].z + ru[q].z, rv[q].w + ru[q].w};
            #pragma unroll
            for (int t = 0; t < 4; t++) {
                float vv = eluf(vals[t]);
                __nv_bfloat16 h = __float2bfloat16(vv);
                hbuf[q * 4 + t] = h;
                lbuf[q * 4 + t] = __float2bfloat16(vv - __bfloat162float(h));
            }
        }
        uint32_t base = sb + st * STG_BYTES;
        uint32_t off = arw * ROWB + halfc * 2;
        *(uint4*)(smem + (base - sb) + off)        = ((uint4*)hbuf)[0];
        *(uint4*)(smem + (base - sb) + off + 16)   = ((uint4*)hbuf)[1];
        *(uint4*)(smem + (base - sb) + 10240 + off)      = ((uint4*)lbuf)[0];
        *(uint4*)(smem + (base - sb) + 10240 + off + 16) = ((uint4*)lbuf)[1];
    };

    const int wm = warp & 1, wn = warp >> 1;
    const int mbase = wm * 64, nbase = wn * 32;

    float acc[4][4][4];
    #pragma unroll
    for (int mi = 0; mi < 4; mi++)
        #pragma unroll
        for (int ni = 0; ni < 4; ni++)
            #pragma unroll
            for (int q = 0; q < 4; q++) acc[mi][ni][q] = 0.f;

    const int lr = lane & 7, seg = lane >> 3;
    const int arowf = mbase + (seg & 1) * 8 + lr;
    const int acolq = (seg >> 1) * 8;
    const int brow = nbase + lr;
    const int bcolq = (seg & 1) * 8;

    // prologue: fill stage 0
    loadA(0);
    issueB(0, 0);
    storeA(0);
    CP_WAIT(0);
    __syncthreads();

    const int NSTEP = Kdim >> 5;
    #pragma unroll 1
    for (int s = 0; s < NSTEP; s++) {
        if (s + 1 < NSTEP) {
            loadA((s + 1) * 32);
            issueB((s + 1) & 1, (s + 1) * 32);
        }
        uint32_t base = sb + (s & 1) * STG_BYTES;
        uint32_t bAh = base, bAl = base + 10240, bBh = base + 20480, bBl = base + 30720;
        #pragma unroll
        for (int ks = 0; ks < 2; ks++) {
            int acol = ks * 16 + acolq;
            int bcol = ks * 16 + bcolq;
            uint32_t ah[4][4], al_[4][4], bh[4][2], bl[4][2];
            #pragma unroll
            for (int mi = 0; mi < 4; mi++) {
                LDSM_X4(ah[mi][0], ah[mi][1], ah[mi][2], ah[mi][3],
                        bAh + (arowf + mi * 16) * ROWB + acol * 2);
                LDSM_X4(al_[mi][0], al_[mi][1], al_[mi][2], al_[mi][3],
                        bAl + (arowf + mi * 16) * ROWB + acol * 2);
            }
            #pragma unroll
            for (int ni = 0; ni < 4; ni++) {
                LDSM_X2(bh[ni][0], bh[ni][1], bBh + (brow + ni * 8) * ROWB + bcol * 2);
                LDSM_X2(bl[ni][0], bl[ni][1], bBl + (brow + ni * 8) * ROWB + bcol * 2);
            }
            #pragma unroll
            for (int mi = 0; mi < 4; mi++)
                #pragma unroll
                for (int ni = 0; ni < 4; ni++) {
                    MMA16816(acc[mi][ni], ah[mi][0], ah[mi][1], ah[mi][2], ah[mi][3],
                             bh[ni][0], bh[ni][1]);
                    MMA16816(acc[mi][ni], ah[mi][0], ah[mi][1], ah[mi][2], ah[mi][3],
                             bl[ni][0], bl[ni][1]);
                    MMA16816(acc[mi][ni], al_[mi][0], al_[mi][1], al_[mi][2], al_[mi][3],
                             bh[ni][0], bh[ni][1]);
                }
        }
        if (s + 1 < NSTEP) {
            storeA((s + 1) & 1);
            CP_WAIT(0);
        }
        __syncthreads();
    }

    // epilogue: stage elu(acc+bias) per edge, mean over 4 edges
    const int gq = lane >> 2, tq = lane & 3;
    float* stg = (float*)smem;
    #pragma unroll
    for (int mi = 0; mi < 4; mi++)
        #pragma unroll
        for (int ni = 0; ni < 4; ni++)
            #pragma unroll
            for (int half = 0; half < 2; half++) {
                int ml = mbase + mi * 16 + gq + half * 8;
                int nl = nbase + ni * 8 + tq * 2;
                stg[ml * 132 + nl]     = eluf(acc[mi][ni][half * 2 + 0] + sbias[nl]);
                stg[ml * 132 + nl + 1] = eluf(acc[mi][ni][half * 2 + 1] + sbias[nl + 1]);
            }
    __syncthreads();
    for (int i = tid; i < 32 * 128; i += 256) {
        int pl = i >> 7, c = i & 127;
        float s4 = stg[(pl * 4 + 0) * 132 + c] + stg[(pl * 4 + 1) * 132 + c]
                 + stg[(pl * 4 + 2) * 132 + c] + stg[(pl * 4 + 3) * 132 + c];
        float v = 0.25f * s4;
        size_t pm = (m0 >> 2) + pl;
        if (of) of[pm * (size_t)ldof + n0 + c] = v;
        __nv_bfloat16 h = __float2bfloat16(v);
        oh[pm * (size_t)KP1 + obase + n0 + c] = h;
        ol[pm * (size_t)KP1 + obase + n0 + c] = __float2bfloat16(v - __bfloat162float(h));
    }
}

// ---------------- KNN ----------------
template<int C>
__global__ void __launch_bounds__(128) knn_kernel(const float* __restrict__ x,
                                                  int* __restrict__ out_idx) {
    extern __shared__ float sm[];
    float* sx = sm;
    float* sn = sm + NN * C;
    int b = blockIdx.x, t = threadIdx.x;
    const float* xb = x + (size_t)b * NN * C;
    for (int i = t; i < NN * C; i += 128) sx[i] = xb[i];
    __syncthreads();
    float nrm = 0.f;
    float rx[C];
    #pragma unroll
    for (int c = 0; c < C; c++) { rx[c] = sx[t * C + c]; nrm += rx[c] * rx[c]; }
    sn[t] = nrm;
    __syncthreads();

    float bd0 = 3e38f, bd1 = 3e38f, bd2 = 3e38f, bd3 = 3e38f;
    int   bi0 = 0, bi1 = 0, bi2 = 0, bi3 = 0;
    for (int j = 0; j < NN; j++) {
        float dot = 0.f;
        if (C % 4 == 0) {
            #pragma unroll
            for (int c = 0; c < C; c += 4) {
                float4 v = *reinterpret_cast<const float4*>(&sx[j * C + c]);
                dot += rx[c] * v.x + rx[c+1] * v.y + rx[c+2] * v.z + rx[c+3] * v.w;
            }
        } else {
            #pragma unroll
            for (int c = 0; c < C; c++) dot += rx[c] * sx[j * C + c];
        }
        float d = nrm + sn[j] - 2.f * dot;
        if (j == t) d += 1e9f;
        if (d < bd3) {
            if (d < bd0)      { bd3=bd2;bi3=bi2; bd2=bd1;bi2=bi1; bd1=bd0;bi1=bi0; bd0=d;bi0=j; }
            else if (d < bd1) { bd3=bd2;bi3=bi2; bd2=bd1;bi2=bi1; bd1=d;bi1=j; }
            else if (d < bd2) { bd3=bd2;bi3=bi2; bd2=d;bi2=j; }
            else              { bd3=d;bi3=j; }
        }
    }
    int* o = out_idx + ((size_t)b * NN + t) * KK;
    o[0] = bi0; o[1] = bi1; o[2] = bi2; o[3] = bi3;
}

// ---------------- EdgeConv stage 1 (fp32, small): U = X@W1b ; V = X@W1a - U + b1 ----------------
template<int C, int H>
__global__ void __launch_bounds__(256) stage1_kernel(const float* __restrict__ x,
                                                     const float* __restrict__ w1,
                                                     const float* __restrict__ b1,
                                                     float* __restrict__ U,
                                                     float* __restrict__ V) {
    const int XS = 132;
    extern __shared__ float sm[];
    float* XT = sm;
    float* Ba = sm + C * XS;
    float* Bb = Ba + 16 * 64;
    int b = blockIdx.x;
    int tid = threadIdx.x;
    int tx = tid & 15, ty = tid >> 4;
    const float* xb = x + (size_t)b * NN * C;
    for (int i = tid; i < NN * C; i += 256) {
        int p = i / C, c = i % C;
        XT[c * XS + p] = xb[i];
    }
    __syncthreads();

    const int NBT = (H + 63) / 64;
    for (int nb = 0; nb < NBT; nb++) {
        float au[8][4], aw[8][4];
        #pragma unroll
        for (int r = 0; r < 8; r++)
            #pragma unroll
            for (int c = 0; c < 4; c++) { au[r][c] = 0.f; aw[r][c] = 0.f; }

        for (int c0 = 0; c0 < C; c0 += 16) {
            int kc = (C - c0 < 16) ? (C - c0) : 16;
            __syncthreads();
            for (int li = tid; li < 16 * 64; li += 256) {
                int kk = li >> 6, n = li & 63;
                int h = nb * 64 + n;
                float va = 0.f, vb = 0.f;
                if (kk < kc && h < H) {
                    va = w1[(size_t)(c0 + kk) * H + h];
                    vb = w1[(size_t)(C + c0 + kk) * H + h];
                }
                Ba[kk * 64 + n] = va;
                Bb[kk * 64 + n] = vb;
            }
            __syncthreads();
            for (int kk = 0; kk < kc; kk++) {
                float4 a0 = *reinterpret_cast<float4*>(&XT[(c0 + kk) * XS + ty * 8]);
                float4 a1 = *reinterpret_cast<float4*>(&XT[(c0 + kk) * XS + ty * 8 + 4]);
                float4 va = *reinterpret_cast<float4*>(&Ba[kk * 64 + tx * 4]);
                float4 vb = *reinterpret_cast<float4*>(&Bb[kk * 64 + tx * 4]);
                float a[8]  = {a0.x, a0.y, a0.z, a0.w, a1.x, a1.y, a1.z, a1.w};
                float wa[4] = {va.x, va.y, va.z, va.w};
                float wb[4] = {vb.x, vb.y, vb.z, vb.w};
                #pragma unroll
                for (int r = 0; r < 8; r++)
                    #pragma unroll
                    for (int c = 0; c < 4; c++) {
                        au[r][c] = fmaf(a[r], wb[c], au[r][c]);
                        aw[r][c] = fmaf(a[r], wa[c], aw[r][c]);
                    }
            }
        }
        #pragma unroll
        for (int r = 0; r < 8; r++) {
            int p = ty * 8 + r;
            size_t base = ((size_t)b * NN + p) * H;
            #pragma unroll
            for (int c = 0; c < 4; c++) {
                int h = nb * 64 + tx * 4 + c;
                if (h < H) {
                    float u = au[r][c];
                    U[base + h] = u;
                    V[base + h] = aw[r][c] - u + b1[h];
                }
            }
        }
    }
}

// ---------------- EdgeConv stage 2 fp32 (ec1 only) + hcat split write ----------------
template<int H, int COUT>
__global__ void __launch_bounds__(256) stage2_kernel(const float* __restrict__ U,
                                                     const float* __restrict__ V,
                                                     const int* __restrict__ idx,
                                                     const float* __restrict__ w2,
                                                     const float* __restrict__ b2,
                                                     float* __restrict__ out,
                                                     __nv_bfloat16* __restrict__ oh,
                                                     __nv_bfloat16* __restrict__ ol,
                                                     int obase) {
    const int ES = 132;
    extern __shared__ float sm[];
    float* M1 = sm;
    float* Bs = sm + H * ES;
    int b = blockIdx.x, pt = blockIdx.y;
    int tid = threadIdx.x;
    int tx = tid & 15, ty = tid >> 4;
    int p0 = pt * 32;

    {
        int e = tid & 127, s = tid >> 7;
        int pl = e >> 2, kk = e & 3;
        int p = p0 + pl;
        int j = idx[((size_t)b * NN + p) * KK + kk];
        const float* vp = V + ((size_t)b * NN + p) * H;
        const float* up = U + ((size_t)b * NN + j) * H;
        int h0 = s * (H / 2), h1 = h0 + H / 2;
        for (int h = h0; h < h1; h++)
            M1[h * ES + e] = eluf(vp[h] + up[h]);
    }
    __syncthreads();

    const int NBT = COUT / 64;
    for (int nb = 0; nb < NBT; nb++) {
        float acc[8][4];
        #pragma unroll
        for (int r = 0; r < 8; r++)
            #pragma unroll
            for (int c = 0; c < 4; c++) acc[r][c] = 0.f;

        for (int k0 = 0; k0 < H; k0 += 16) {
            __syncthreads();
            {
                int kk = tid >> 4, nq = tid & 15;
                *reinterpret_cast<float4*>(&Bs[kk * 64 + nq * 4]) =
                    *reinterpret_cast<const float4*>(&w2[(size_t)(k0 + kk) * COUT + nb * 64 + nq * 4]);
            }
            __syncthreads();
            #pragma unroll
            for (int kk = 0; kk < 16; kk++) {
                float4 a0 = *reinterpret_cast<float4*>(&M1[(k0 + kk) * ES + ty * 8]);
                float4 a1 = *reinterpret_cast<float4*>(&M1[(k0 + kk) * ES + ty * 8 + 4]);
                float4 b4 = *reinterpret_cast<float4*>(&Bs[kk * 64 + tx * 4]);
                float a[8]  = {a0.x, a0.y, a0.z, a0.w, a1.x, a1.y, a1.z, a1.w};
                float wv[4] = {b4.x, b4.y, b4.z, b4.w};
                #pragma unroll
                for (int r = 0; r < 8; r++)
                    #pragma unroll
                    for (int c = 0; c < 4; c++)
                        acc[r][c] = fmaf(a[r], wv[c], acc[r][c]);
            }
        }
        #pragma unroll
        for (int q = 0; q < 2; q++) {
            int p = p0 + ty * 2 + q;
            size_t row = (size_t)b * NN + p;
            #pragma unroll
            for (int c = 0; c < 4; c++) {
                int o = nb * 64 + tx * 4 + c;
                float bias = b2[o];
                float s = 0.f;
                #pragma unroll
                for (int r = 0; r < 4; r++) s += eluf(acc[q * 4 + r][c] + bias);
                float v = 0.25f * s;
                out[row * COUT + o] = v;
                __nv_bfloat16 h = __float2bfloat16(v);
                oh[row * KP1 + obase + o] = h;
                ol[row * KP1 + obase + o] = __float2bfloat16(v - __bfloat162float(h));
            }
        }
    }
}

// ---------------- final tiny GEMM ----------------
__global__ void final_kernel(const float* __restrict__ b3, float* __restrict__ out) {
    int warp = (blockIdx.x * blockDim.x + threadIdx.x) >> 5;
    int lane = threadIdx.x & 31;
    if (warp >= MTOT) return;
    const float* row = g_h2 + (size_t)warp * 256;
    float a0 = 0.f, a1 = 0.f;
    for (int k = lane; k < 256; k += 32) {
        float v = row[k];
        a0 = fmaf(v, g_W3p[k * 2 + 0], a0);
        a1 = fmaf(v, g_W3p[k * 2 + 1], a1);
    }
    #pragma unroll
    for (int off = 16; off; off >>= 1) {
        a0 += __shfl_down_sync(0xFFFFFFFFu, a0, off);
        a1 += __shfl_down_sync(0xFFFFFFFFu, a1, off);
    }
    if (lane == 0) {
        out[(size_t)warp * 2 + 0] = a0 + b3[0];
        out[(size_t)warp * 2 + 1] = a1 + b3[1];
    }
}

// ---------------- launch ----------------
extern "C" void kernel_launch(void* const* d_in, const int* in_sizes, int n_in,
                              void* d_out, int out_size) {
    const float* coords = (const float*)d_in[0];
    const float* feats  = (const float*)d_in[1];
    const float* c1w1 = (const float*)d_in[2];  const float* c1b1 = (const float*)d_in[3];
    const float* c1w2 = (const float*)d_in[4];  const float* c1b2 = (const float*)d_in[5];
    const float* c2w1 = (const float*)d_in[6];  const float* c2b1 = (const float*)d_in[7];
    const float* c2w2 = (const float*)d_in[8];  const float* c2b2 = (const float*)d_in[9];
    const float* c3w1 = (const float*)d_in[10]; const float* c3b1 = (const float*)d_in[11];
    const float* c3w2 = (const float*)d_in[12]; const float* c3b2 = (const float*)d_in[13];
    const float* ow1  = (const float*)d_in[14]; const float* ob1  = (const float*)d_in[15];
    const float* ow2  = (const float*)d_in[16]; const float* ob2  = (const float*)d_in[17];
    const float* ow3  = (const float*)d_in[18]; const float* ob3  = (const float*)d_in[19];
    float* out = (float*)d_out;

    float *out1p, *out2p, *Up, *Vp, *UVp, *h2p, *b1pp, *b2pp, *W3pp, *sb1p;
    __nv_bfloat16 *A1hp, *A1lp, *h1hp, *h1lp;
    __nv_bfloat16 *Bt1hp, *Bt1lp, *Bt2hp, *Bt2lp, *Bc2hp, *Bc2lp, *Bc3hp, *Bc3lp, *Bs1hp, *Bs1lp;
    int* idxp;
    cudaGetSymbolAddress((void**)&out1p, g_out1);
    cudaGetSymbolAddress((void**)&out2p, g_out2);
    cudaGetSymbolAddress((void**)&Up,    g_U);
    cudaGetSymbolAddress((void**)&Vp,    g_V);
    cudaGetSymbolAddress((void**)&UVp,   g_UV);
    cudaGetSymbolAddress((void**)&idxp,  g_idx);
    cudaGetSymbolAddress((void**)&h2p,   g_h2);
    cudaGetSymbolAddress((void**)&b1pp,  g_b1p);
    cudaGetSymbolAddress((void**)&b2pp,  g_b2p);
    cudaGetSymbolAddress((void**)&W3pp,  g_W3p);
    cudaGetSymbolAddress((void**)&sb1p,  g_sb1);
    cudaGetSymbolAddress((void**)&A1hp,  g_A1h);
    cudaGetSymbolAddress((void**)&A1lp,  g_A1l);
    cudaGetSymbolAddress((void**)&h1hp,  g_h1h);
    cudaGetSymbolAddress((void**)&h1lp,  g_h1l);
    cudaGetSymbolAddress((void**)&Bt1hp, g_Bt1h);
    cudaGetSymbolAddress((void**)&Bt1lp, g_Bt1l);
    cudaGetSymbolAddress((void**)&Bt2hp, g_Bt2h);
    cudaGetSymbolAddress((void**)&Bt2lp, g_Bt2l);
    cudaGetSymbolAddress((void**)&Bc2hp, g_Bc2h);
    cudaGetSymbolAddress((void**)&Bc2lp, g_Bc2l);
    cudaGetSymbolAddress((void**)&Bc3hp, g_Bc3h);
    cudaGetSymbolAddress((void**)&Bc3lp, g_Bc3l);
    cudaGetSymbolAddress((void**)&Bs1hp, g_Bs1h);
    cudaGetSymbolAddress((void**)&Bs1lp, g_Bs1l);

    const int sm_knn2   = (NN * 2 + NN) * 4;
    const int sm_knn64  = (NN * 64 + NN) * 4;
    const int sm_knn128 = (NN * 128 + NN) * 4;
    const int sm_s1_a = (5 * 132 + 2 * 16 * 64) * 4;
    const int sm_s1_b = (64 * 132 + 2 * 16 * 64) * 4;
    const int sm_s2_a = (32 * 132 + 16 * 64) * 4;
    const int sm_gemm = 2 * STG_BYTES + 1024;   // 82944

    cudaFuncSetAttribute(knn_kernel<128>, cudaFuncAttributeMaxDynamicSharedMemorySize, sm_knn128);
    cudaFuncSetAttribute(gemm_mma,        cudaFuncAttributeMaxDynamicSharedMemorySize, sm_gemm);
    cudaFuncSetAttribute(gemm_edge,       cudaFuncAttributeMaxDynamicSharedMemorySize, sm_gemm);

    // weight prep
    pad_copy_kernel<<<2, 256>>>(b1pp, ob1, 1, 453, 1, 512);
    pad_copy_kernel<<<1, 256>>>(b2pp, ob2, 1, 226, 1, 256);
    pad_copy_kernel<<<2, 256>>>(W3pp, ow3, 226, 2, 256, 2);
    split_w1p_kernel<<<240, 256>>>(ow1, Bt1hp, Bt1lp);
    split_w_kernel<<<128, 256>>>(ow2, 453, 226, Bt2hp, Bt2lp, 256, KP2);
    split_w_kernel<<<16, 256>>>(c2w2, 96, 128, Bc2hp, Bc2lp, 128, 96);
    split_w_kernel<<<48, 256>>>(c3w2, 192, 256, Bc3hp, Bc3lp, 256, 192);
    split_s1w_kernel<<<48, 256>>>(c3w1, c3b1, Bs1hp, Bs1lp, sb1p);
    hcat_edges_kernel<<<4096, 256>>>(feats);

    // ---- edgeconv 1 (fp32: tiny) ----
    knn_kernel<2><<<BB, 128, sm_knn2>>>(coords, idxp);
    stage1_kernel<5, 32><<<BB, 256, sm_s1_a>>>(feats, c1w1, c1b1, Up, Vp);
    stage2_kernel<32, 64><<<dim3(BB, 4), 256, sm_s2_a>>>(Up, Vp, idxp, c1w2, c1b2,
                                                         out1p, A1hp, A1lp, 8);

    // ---- edgeconv 2 ----
    knn_kernel<64><<<BB, 128, sm_knn64>>>(out1p, idxp);
    stage1_kernel<64, 96><<<BB, 256, sm_s1_b>>>(out1p, c2w1, c2b1, Up, Vp);
    gemm_edge<<<dim3(ME / 128, 1), 256, sm_gemm>>>(Up, Vp, 96, idxp, Bc2hp, Bc2lp, c2b2,
                                                   out2p, 128, A1hp, A1lp, 72, 96);

    // ---- edgeconv 3 ----
    knn_kernel<128><<<BB, 128, sm_knn128>>>(out2p, idxp);
    gemm_mma<<<dim3(MTOT / 128, 3), 256, sm_gemm>>>(A1hp + 72, A1lp + 72, KP1,
                                                    Bs1hp, Bs1lp, sb1p,
                                                    nullptr, nullptr, UVp, 384, 128, 3);
    gemm_edge<<<dim3(ME / 128, 2), 256, sm_gemm>>>(UVp, UVp + 192, 384, idxp, Bc3hp, Bc3lp, c3b2,
                                                   nullptr, 0, A1hp, A1lp, 200, 192);

    // ---- head ----
    gemm_mma<<<dim3(MTOT / 128, 4), 256, sm_gemm>>>(A1hp, A1lp, KP1, Bt1hp, Bt1lp, b1pp,
                                                    h1hp, h1lp, nullptr, KP2, KP1, 0);
    gemm_mma<<<dim3(MTOT / 128, 2), 256, sm_gemm>>>(h1hp, h1lp, KP2, Bt2hp, Bt2lp, b2pp,
                                                    nullptr, nullptr, h2p, 256, KP2, 1);
    final_kernel<<<MTOT / 8, 256>>>(ob3, out);
}

// round 6
// speedup vs baseline: 1.2468x; 1.2468x over previous
#include <cuda_runtime.h>
#include <cuda_bf16.h>
#include <math.h>
#include <stdint.h>

#define BB 1024
#define NN 128
#define KK 4
#define MTOT (BB*NN)     // 131072
#define ME  (MTOT*KK)    // 524288 edges
#define KP1 480          // hcat padded K (head GEMM1)
#define KP2 512          // head GEMM2 K

// ---------------- scratch (device globals: allocation-free) ----------------
__device__ float g_out1[MTOT*64];
__device__ float g_out2[MTOT*128];
__device__ float g_U[MTOT*96];
__device__ float g_V[MTOT*96];
__device__ float g_UV[(size_t)MTOT*384];     // stage1-ec3 out: [U(192)|V(192)]
__device__ int   g_idx[MTOT*KK];
__device__ float g_h2[(size_t)MTOT*256];
__device__ float g_b1p[512];
__device__ float g_b2p[256];
__device__ float g_W3p[256*2];
__device__ float g_sb1[384];

// bf16 split operands (16B aligned)
// hcat cols: [0..5)=feats [5..8)=0 [8..72)=out1 [72..200)=out2 [200..456)=out3 [456..480)=0
__device__ __align__(16) __nv_bfloat16 g_A1h[(size_t)MTOT*KP1];
__device__ __align__(16) __nv_bfloat16 g_A1l[(size_t)MTOT*KP1];
__device__ __align__(16) __nv_bfloat16 g_h1h[(size_t)MTOT*KP2];
__device__ __align__(16) __nv_bfloat16 g_h1l[(size_t)MTOT*KP2];
__device__ __align__(16) __nv_bfloat16 g_Eh[(size_t)ME*192];
__device__ __align__(16) __nv_bfloat16 g_El[(size_t)ME*192];
__device__ __align__(16) __nv_bfloat16 g_Bt1h[512*KP1];
__device__ __align__(16) __nv_bfloat16 g_Bt1l[512*KP1];
__device__ __align__(16) __nv_bfloat16 g_Bt2h[256*KP2];
__device__ __align__(16) __nv_bfloat16 g_Bt2l[256*KP2];
__device__ __align__(16) __nv_bfloat16 g_Bc2h[128*96];
__device__ __align__(16) __nv_bfloat16 g_Bc2l[128*96];
__device__ __align__(16) __nv_bfloat16 g_Bc3h[256*192];
__device__ __align__(16) __nv_bfloat16 g_Bc3l[256*192];
__device__ __align__(16) __nv_bfloat16 g_Bs1h[384*128];
__device__ __align__(16) __nv_bfloat16 g_Bs1l[384*128];

__device__ __forceinline__ float eluf(float x) { return x > 0.f ? x : expm1f(x); }

__device__ __forceinline__ uint32_t smem_u32(const void* p) {
    uint32_t a;
    asm("{ .reg .u64 t; cvta.to.shared.u64 t, %1; cvt.u32.u64 %0, t; }" : "=r"(a) : "l"(p));
    return a;
}
__device__ __forceinline__ void cp16(uint32_t dst, const void* src) {
    asm volatile("cp.async.cg.shared.global [%0], [%1], 16;" :: "r"(dst), "l"(src));
}
#define CP_COMMIT() asm volatile("cp.async.commit_group;" ::: "memory")
#define CP_WAIT(n)  asm volatile("cp.async.wait_group %0;" :: "n"(n) : "memory")

#define LDSM_X4(r0, r1, r2, r3, addr) \
    asm volatile("ldmatrix.sync.aligned.m8n8.x4.shared.b16 {%0,%1,%2,%3}, [%4];" \
        : "=r"(r0), "=r"(r1), "=r"(r2), "=r"(r3) : "r"(addr))
#define LDSM_X2(r0, r1, addr) \
    asm volatile("ldmatrix.sync.aligned.m8n8.x2.shared.b16 {%0,%1}, [%2];" \
        : "=r"(r0), "=r"(r1) : "r"(addr))

#define MMA16816(d, a0, a1, a2, a3, b0, b1) \
    asm volatile("mma.sync.aligned.m16n8k16.row.col.f32.bf16.bf16.f32 " \
        "{%0,%1,%2,%3}, {%4,%5,%6,%7}, {%8,%9}, {%0,%1,%2,%3};" \
        : "+f"((d)[0]), "+f"((d)[1]), "+f"((d)[2]), "+f"((d)[3]) \
        : "r"(a0), "r"(a1), "r"(a2), "r"(a3), "r"(b0), "r"(b1))

#define STG_BYTES 40960
#define ROWB 80

// ---------------- weight prep ----------------
__global__ void pad_copy_kernel(float* __restrict__ dst, const float* __restrict__ src,
                                int sr, int sc, int dr, int dc) {
    int tot = dr * dc;
    for (int i = blockIdx.x * blockDim.x + threadIdx.x; i < tot; i += gridDim.x * blockDim.x) {
        int r = i / dc, c = i % dc;
        dst[i] = (r < sr && c < sc) ? src[r * sc + c] : 0.f;
    }
}

__global__ void split_w_kernel(const float* __restrict__ W, int sr, int sc,
                               __nv_bfloat16* __restrict__ oh, __nv_bfloat16* __restrict__ ol,
                               int Np, int Kp) {
    int tot = Np * Kp;
    for (int i = blockIdx.x * blockDim.x + threadIdx.x; i < tot; i += gridDim.x * blockDim.x) {
        int n = i / Kp, k = i % Kp;
        float v = (k < sr && n < sc) ? W[k * sc + n] : 0.f;
        __nv_bfloat16 h = __float2bfloat16(v);
        oh[i] = h;
        ol[i] = __float2bfloat16(v - __bfloat162float(h));
    }
}

// head GEMM1 weight with hcat-permuted K rows: [512][KP1]
__global__ void split_w1p_kernel(const float* __restrict__ W,
                                 __nv_bfloat16* __restrict__ oh, __nv_bfloat16* __restrict__ ol) {
    int tot = 512 * KP1;
    for (int i = blockIdx.x * blockDim.x + threadIdx.x; i < tot; i += gridDim.x * blockDim.x) {
        int n = i / KP1, k = i % KP1;
        int src = -1;
        if (k < 5)                    src = k;
        else if (k >= 8 && k < 72)    src = 5 + (k - 8);
        else if (k >= 72 && k < 200)  src = 69 + (k - 72);
        else if (k >= 200 && k < 456) src = 197 + (k - 200);
        float v = (src >= 0 && n < 453) ? W[(size_t)src * 453 + n] : 0.f;
        __nv_bfloat16 h = __float2bfloat16(v);
        oh[i] = h;
        ol[i] = __float2bfloat16(v - __bfloat162float(h));
    }
}

// stage1-ec3 combined weight: rows 0..191 = W1b^T, 192..383 = (W1a-W1b)^T; bias [0|b1]
__global__ void split_s1w_kernel(const float* __restrict__ w1, const float* __restrict__ b1,
                                 __nv_bfloat16* __restrict__ oh, __nv_bfloat16* __restrict__ ol,
                                 float* __restrict__ biasv) {
    int tot = 384 * 128;
    int t0 = blockIdx.x * blockDim.x + threadIdx.x;
    for (int i = t0; i < tot; i += gridDim.x * blockDim.x) {
        int n = i >> 7, k = i & 127;
        float v;
        if (n < 192) v = w1[(size_t)(128 + k) * 192 + n];
        else         v = w1[(size_t)k * 192 + (n - 192)] - w1[(size_t)(128 + k) * 192 + (n - 192)];
        __nv_bfloat16 h = __float2bfloat16(v);
        oh[i] = h;
        ol[i] = __float2bfloat16(v - __bfloat162float(h));
    }
    if (t0 < 384) biasv[t0] = (t0 < 192) ? 0.f : b1[t0 - 192];
}

// fill hcat edge cols: 0..8 (feats+pad) and 456..480 (pad)
__global__ void hcat_edges_kernel(const float* __restrict__ feats) {
    size_t total = (size_t)MTOT * 32;
    for (size_t i = (size_t)blockIdx.x * blockDim.x + threadIdx.x; i < total;
         i += (size_t)gridDim.x * blockDim.x) {
        size_t m = i >> 5;
        int cq = (int)(i & 31);
        int c = (cq < 8) ? cq : 448 + cq;
        float v = (c < 5) ? feats[m * 5 + c] : 0.f;
        __nv_bfloat16 h = __float2bfloat16(v);
        g_A1h[m * KP1 + c] = h;
        g_A1l[m * KP1 + c] = __float2bfloat16(v - __bfloat162float(h));
    }
}

// ---------------- edge gather: E[e][c] = elu(V[p][c] + U[j][c]) -> bf16 split ----------------
template<int H>
__global__ void edge_gather(const float* __restrict__ Ub, const float* __restrict__ Vb,
                            int suv, const int* __restrict__ idx,
                            __nv_bfloat16* __restrict__ Eh, __nv_bfloat16* __restrict__ El) {
    const int GP = H / 8;
    size_t total = (size_t)ME * GP;
    for (size_t i = (size_t)blockIdx.x * blockDim.x + threadIdx.x; i < total;
         i += (size_t)gridDim.x * blockDim.x) {
        size_t e = i / GP;
        int g = (int)(i - e * GP);
        int p = (int)(e >> 2);
        int j = idx[e];
        int jg = (p & ~127) + j;
        const float4* vp = (const float4*)(Vb + (size_t)p * suv + g * 8);
        const float4* up = (const float4*)(Ub + (size_t)jg * suv + g * 8);
        float4 v0 = vp[0], v1 = vp[1], u0 = up[0], u1 = up[1];
        float r[8] = {v0.x+u0.x, v0.y+u0.y, v0.z+u0.z, v0.w+u0.w,
                      v1.x+u1.x, v1.y+u1.y, v1.z+u1.z, v1.w+u1.w};
        __nv_bfloat16 hh[8], ll[8];
        #pragma unroll
        for (int q = 0; q < 8; q++) {
            float vv = eluf(r[q]);
            hh[q] = __float2bfloat16(vv);
            ll[q] = __float2bfloat16(vv - __bfloat162float(hh[q]));
        }
        *(uint4*)&Eh[e * H + g * 8] = *(uint4*)hh;
        *(uint4*)&El[e * H + g * 8] = *(uint4*)ll;
    }
}

// ================= bf16x3-split tensor-core GEMM (mma.sync) =================
// out = post(A[M x Kdim(lda)] @ B^T[N x Kdim] + bias), via ah*bh + ah*bl + al*bh.
// mode 0: elu + bf16-split (oh/ol at ldoh, obase). mode 1: elu + fp32 (of). mode 3: plain fp32.
// mode 2: per-edge elu then mean over 4 rows -> fp32 of (opt, ldof) + bf16 split oh/ol
//         (opt, at ldoh with obase column offset).
__global__ void __launch_bounds__(256) gemm_mma(
    const __nv_bfloat16* __restrict__ Ah, const __nv_bfloat16* __restrict__ Al, int lda,
    const __nv_bfloat16* __restrict__ Bh, const __nv_bfloat16* __restrict__ Bl,
    const float* __restrict__ bias,
    __nv_bfloat16* __restrict__ oh, __nv_bfloat16* __restrict__ ol, int ldoh, int obase,
    float* __restrict__ of, int ldof, int Kdim, int mode) {
    extern __shared__ char smem[];
    float* sbias = (float*)(smem + 2 * STG_BYTES);

    const int tid = threadIdx.x;
    const int warp = tid >> 5, lane = tid & 31;
    const size_t m0 = (size_t)blockIdx.x * 128;
    const int n0 = blockIdx.y * 128;
    const uint32_t sb = smem_u32(smem);

    if (tid < 128) sbias[tid] = bias[n0 + tid];

    auto issue = [&](int st, int k0) {
        uint32_t base = sb + st * STG_BYTES;
        #pragma unroll
        for (int i = tid; i < 2048; i += 256) {
            int mat = i >> 9, j = i & 511, r = j >> 2, c = j & 3;
            uint32_t daddr = base + mat * 10240 + r * ROWB + c * 16;
            const __nv_bfloat16* g;
            if (mat == 0)      g = &Ah[(m0 + r) * lda + k0 + c * 8];
            else if (mat == 1) g = &Al[(m0 + r) * lda + k0 + c * 8];
            else if (mat == 2) g = &Bh[(size_t)(n0 + r) * Kdim + k0 + c * 8];
            else               g = &Bl[(size_t)(n0 + r) * Kdim + k0 + c * 8];
            cp16(daddr, g);
        }
        CP_COMMIT();
    };

    const int wm = warp & 1, wn = warp >> 1;
    const int mbase = wm * 64, nbase = wn * 32;

    float acc[4][4][4];
    #pragma unroll
    for (int mi = 0; mi < 4; mi++)
        #pragma unroll
        for (int ni = 0; ni < 4; ni++)
            #pragma unroll
            for (int q = 0; q < 4; q++) acc[mi][ni][q] = 0.f;

    const int lr = lane & 7, seg = lane >> 3;
    const int arow = mbase + (seg & 1) * 8 + lr;
    const int acolq = (seg >> 1) * 8;
    const int brow = nbase + lr;
    const int bcolq = (seg & 1) * 8;

    issue(0, 0);

    const int NSTEP = Kdim >> 5;
    #pragma unroll 1
    for (int s = 0; s < NSTEP; s++) {
        if (s + 1 < NSTEP) { issue((s + 1) & 1, (s + 1) * 32); CP_WAIT(1); }
        else               { CP_WAIT(0); }
        __syncthreads();
        uint32_t base = sb + (s & 1) * STG_BYTES;
        uint32_t bAh = base, bAl = base + 10240, bBh = base + 20480, bBl = base + 30720;

        #pragma unroll
        for (int ks = 0; ks < 2; ks++) {
            int acol = ks * 16 + acolq;
            int bcol = ks * 16 + bcolq;
            uint32_t ah[4][4], al_[4][4], bh[4][2], bl[4][2];
            #pragma unroll
            for (int mi = 0; mi < 4; mi++) {
                LDSM_X4(ah[mi][0], ah[mi][1], ah[mi][2], ah[mi][3],
                        bAh + (arow + mi * 16) * ROWB + acol * 2);
                LDSM_X4(al_[mi][0], al_[mi][1], al_[mi][2], al_[mi][3],
                        bAl + (arow + mi * 16) * ROWB + acol * 2);
            }
            #pragma unroll
            for (int ni = 0; ni < 4; ni++) {
                LDSM_X2(bh[ni][0], bh[ni][1], bBh + (brow + ni * 8) * ROWB + bcol * 2);
                LDSM_X2(bl[ni][0], bl[ni][1], bBl + (brow + ni * 8) * ROWB + bcol * 2);
            }
            #pragma unroll
            for (int mi = 0; mi < 4; mi++)
                #pragma unroll
                for (int ni = 0; ni < 4; ni++) {
                    MMA16816(acc[mi][ni], ah[mi][0], ah[mi][1], ah[mi][2], ah[mi][3],
                             bh[ni][0], bh[ni][1]);
                    MMA16816(acc[mi][ni], ah[mi][0], ah[mi][1], ah[mi][2], ah[mi][3],
                             bl[ni][0], bl[ni][1]);
                    MMA16816(acc[mi][ni], al_[mi][0], al_[mi][1], al_[mi][2], al_[mi][3],
                             bh[ni][0], bh[ni][1]);
                }
        }
        __syncthreads();
    }

    const int gq = lane >> 2, tq = lane & 3;

    if (mode == 2) {
        // stage elu(acc+bias) for 128 edge rows, then mean over groups of 4
        float* stg = (float*)smem;
        #pragma unroll
        for (int mi = 0; mi < 4; mi++)
            #pragma unroll
            for (int ni = 0; ni < 4; ni++)
                #pragma unroll
                for (int half = 0; half < 2; half++) {
                    int ml = mbase + mi * 16 + gq + half * 8;
                    int nl = nbase + ni * 8 + tq * 2;
                    stg[ml * 132 + nl]     = eluf(acc[mi][ni][half * 2 + 0] + sbias[nl]);
                    stg[ml * 132 + nl + 1] = eluf(acc[mi][ni][half * 2 + 1] + sbias[nl + 1]);
                }
        __syncthreads();
        for (int i = tid; i < 32 * 128; i += 256) {
            int pl = i >> 7, c = i & 127;
            float s4 = stg[(pl * 4 + 0) * 132 + c] + stg[(pl * 4 + 1) * 132 + c]
                     + stg[(pl * 4 + 2) * 132 + c] + stg[(pl * 4 + 3) * 132 + c];
            float v = 0.25f * s4;
            size_t pm = (m0 >> 2) + pl;
            if (of) of[pm * (size_t)ldof + n0 + c] = v;
            __nv_bfloat16 h = __float2bfloat16(v);
            size_t o = pm * (size_t)ldoh + obase + n0 + c;
            oh[o] = h;
            ol[o] = __float2bfloat16(v - __bfloat162float(h));
        }
        return;
    }

    const bool doelu = (mode != 3);
    #pragma unroll
    for (int mi = 0; mi < 4; mi++) {
        #pragma unroll
        for (int ni = 0; ni < 4; ni++) {
            #pragma unroll
            for (int half = 0; half < 2; half++) {
                size_t m = m0 + mbase + mi * 16 + gq + half * 8;
                int nl = nbase + ni * 8 + tq * 2;
                float v0 = acc[mi][ni][half * 2 + 0] + sbias[nl];
                float v1 = acc[mi][ni][half * 2 + 1] + sbias[nl + 1];
                if (doelu) { v0 = eluf(v0); v1 = eluf(v1); }
                if (mode == 0) {
                    size_t o = m * (size_t)ldoh + obase + n0 + nl;
                    __nv_bfloat162 hv, lv;
                    hv.x = __float2bfloat16(v0);
                    hv.y = __float2bfloat16(v1);
                    lv.x = __float2bfloat16(v0 - __bfloat162float(hv.x));
                    lv.y = __float2bfloat16(v1 - __bfloat162float(hv.y));
                    *(__nv_bfloat162*)&oh[o] = hv;
                    *(__nv_bfloat162*)&ol[o] = lv;
                } else {
                    *(float2*)&of[m * (size_t)ldof + n0 + nl] = make_float2(v0, v1);
                }
            }
        }
    }
}

// ---------------- KNN ----------------
template<int C>
__global__ void __launch_bounds__(128) knn_kernel(const float* __restrict__ x,
                                                  int* __restrict__ out_idx) {
    extern __shared__ float sm[];
    float* sx = sm;
    float* sn = sm + NN * C;
    int b = blockIdx.x, t = threadIdx.x;
    const float* xb = x + (size_t)b * NN * C;
    for (int i = t; i < NN * C; i += 128) sx[i] = xb[i];
    __syncthreads();
    float nrm = 0.f;
    float rx[C];
    #pragma unroll
    for (int c = 0; c < C; c++) { rx[c] = sx[t * C + c]; nrm += rx[c] * rx[c]; }
    sn[t] = nrm;
    __syncthreads();

    float bd0 = 3e38f, bd1 = 3e38f, bd2 = 3e38f, bd3 = 3e38f;
    int   bi0 = 0, bi1 = 0, bi2 = 0, bi3 = 0;
    for (int j = 0; j < NN; j++) {
        float dot = 0.f;
        if (C % 4 == 0) {
            #pragma unroll
            for (int c = 0; c < C; c += 4) {
                float4 v = *reinterpret_cast<const float4*>(&sx[j * C + c]);
                dot += rx[c] * v.x + rx[c+1] * v.y + rx[c+2] * v.z + rx[c+3] * v.w;
            }
        } else {
            #pragma unroll
            for (int c = 0; c < C; c++) dot += rx[c] * sx[j * C + c];
        }
        float d = nrm + sn[j] - 2.f * dot;
        if (j == t) d += 1e9f;
        if (d < bd3) {
            if (d < bd0)      { bd3=bd2;bi3=bi2; bd2=bd1;bi2=bi1; bd1=bd0;bi1=bi0; bd0=d;bi0=j; }
            else if (d < bd1) { bd3=bd2;bi3=bi2; bd2=bd1;bi2=bi1; bd1=d;bi1=j; }
            else if (d < bd2) { bd3=bd2;bi3=bi2; bd2=d;bi2=j; }
            else              { bd3=d;bi3=j; }
        }
    }
    int* o = out_idx + ((size_t)b * NN + t) * KK;
    o[0] = bi0; o[1] = bi1; o[2] = bi2; o[3] = bi3;
}

// ---------------- EdgeConv stage 1 (fp32, small): U = X@W1b ; V = X@W1a - U + b1 ----------------
template<int C, int H>
__global__ void __launch_bounds__(256) stage1_kernel(const float* __restrict__ x,
                                                     const float* __restrict__ w1,
                                                     const float* __restrict__ b1,
                                                     float* __restrict__ U,
                                                     float* __restrict__ V) {
    const int XS = 132;
    extern __shared__ float sm[];
    float* XT = sm;
    float* Ba = sm + C * XS;
    float* Bb = Ba + 16 * 64;
    int b = blockIdx.x;
    int tid = threadIdx.x;
    int tx = tid & 15, ty = tid >> 4;
    const float* xb = x + (size_t)b * NN * C;
    for (int i = tid; i < NN * C; i += 256) {
        int p = i / C, c = i % C;
        XT[c * XS + p] = xb[i];
    }
    __syncthreads();

    const int NBT = (H + 63) / 64;
    for (int nb = 0; nb < NBT; nb++) {
        float au[8][4], aw[8][4];
        #pragma unroll
        for (int r = 0; r < 8; r++)
            #pragma unroll
            for (int c = 0; c < 4; c++) { au[r][c] = 0.f; aw[r][c] = 0.f; }

        for (int c0 = 0; c0 < C; c0 += 16) {
            int kc = (C - c0 < 16) ? (C - c0) : 16;
            __syncthreads();
            for (int li = tid; li < 16 * 64; li += 256) {
                int kk = li >> 6, n = li & 63;
                int h = nb * 64 + n;
                float va = 0.f, vb = 0.f;
                if (kk < kc && h < H) {
                    va = w1[(size_t)(c0 + kk) * H + h];
                    vb = w1[(size_t)(C + c0 + kk) * H + h];
                }
                Ba[kk * 64 + n] = va;
                Bb[kk * 64 + n] = vb;
            }
            __syncthreads();
            for (int kk = 0; kk < kc; kk++) {
                float4 a0 = *reinterpret_cast<float4*>(&XT[(c0 + kk) * XS + ty * 8]);
                float4 a1 = *reinterpret_cast<float4*>(&XT[(c0 + kk) * XS + ty * 8 + 4]);
                float4 va = *reinterpret_cast<float4*>(&Ba[kk * 64 + tx * 4]);
                float4 vb = *reinterpret_cast<float4*>(&Bb[kk * 64 + tx * 4]);
                float a[8]  = {a0.x, a0.y, a0.z, a0.w, a1.x, a1.y, a1.z, a1.w};
                float wa[4] = {va.x, va.y, va.z, va.w};
                float wb[4] = {vb.x, vb.y, vb.z, vb.w};
                #pragma unroll
                for (int r = 0; r < 8; r++)
                    #pragma unroll
                    for (int c = 0; c < 4; c++) {
                        au[r][c] = fmaf(a[r], wb[c], au[r][c]);
                        aw[r][c] = fmaf(a[r], wa[c], aw[r][c]);
                    }
            }
        }
        #pragma unroll
        for (int r = 0; r < 8; r++) {
            int p = ty * 8 + r;
            size_t base = ((size_t)b * NN + p) * H;
            #pragma unroll
            for (int c = 0; c < 4; c++) {
                int h = nb * 64 + tx * 4 + c;
                if (h < H) {
                    float u = au[r][c];
                    U[base + h] = u;
                    V[base + h] = aw[r][c] - u + b1[h];
                }
            }
        }
    }
}

// ---------------- EdgeConv stage 2 fp32 (ec1 only) + hcat split write ----------------
template<int H, int COUT>
__global__ void __launch_bounds__(256) stage2_kernel(const float* __restrict__ U,
                                                     const float* __restrict__ V,
                                                     const int* __restrict__ idx,
                                                     const float* __restrict__ w2,
                                                     const float* __restrict__ b2,
                                                     float* __restrict__ out,
                                                     __nv_bfloat16* __restrict__ oh,
                                                     __nv_bfloat16* __restrict__ ol,
                                                     int obase) {
    const int ES = 132;
    extern __shared__ float sm[];
    float* M1 = sm;
    float* Bs = sm + H * ES;
    int b = blockIdx.x, pt = blockIdx.y;
    int tid = threadIdx.x;
    int tx = tid & 15, ty = tid >> 4;
    int p0 = pt * 32;

    {
        int e = tid & 127, s = tid >> 7;
        int pl = e >> 2, kk = e & 3;
        int p = p0 + pl;
        int j = idx[((size_t)b * NN + p) * KK + kk];
        const float* vp = V + ((size_t)b * NN + p) * H;
        const float* up = U + ((size_t)b * NN + j) * H;
        int h0 = s * (H / 2), h1 = h0 + H / 2;
        for (int h = h0; h < h1; h++)
            M1[h * ES + e] = eluf(vp[h] + up[h]);
    }
    __syncthreads();

    const int NBT = COUT / 64;
    for (int nb = 0; nb < NBT; nb++) {
        float acc[8][4];
        #pragma unroll
        for (int r = 0; r < 8; r++)
            #pragma unroll
            for (int c = 0; c < 4; c++) acc[r][c] = 0.f;

        for (int k0 = 0; k0 < H; k0 += 16) {
            __syncthreads();
            {
                int kk = tid >> 4, nq = tid & 15;
                *reinterpret_cast<float4*>(&Bs[kk * 64 + nq * 4]) =
                    *reinterpret_cast<const float4*>(&w2[(size_t)(k0 + kk) * COUT + nb * 64 + nq * 4]);
            }
            __syncthreads();
            #pragma unroll
            for (int kk = 0; kk < 16; kk++) {
                float4 a0 = *reinterpret_cast<float4*>(&M1[(k0 + kk) * ES + ty * 8]);
                float4 a1 = *reinterpret_cast<float4*>(&M1[(k0 + kk) * ES + ty * 8 + 4]);
                float4 b4 = *reinterpret_cast<float4*>(&Bs[kk * 64 + tx * 4]);
                float a[8]  = {a0.x, a0.y, a0.z, a0.w, a1.x, a1.y, a1.z, a1.w};
                float wv[4] = {b4.x, b4.y, b4.z, b4.w};
                #pragma unroll
                for (int r = 0; r < 8; r++)
                    #pragma unroll
                    for (int c = 0; c < 4; c++)
                        acc[r][c] = fmaf(a[r], wv[c], acc[r][c]);
            }
        }
        #pragma unroll
        for (int q = 0; q < 2; q++) {
            int p = p0 + ty * 2 + q;
            size_t row = (size_t)b * NN + p;
            #pragma unroll
            for (int c = 0; c < 4; c++) {
                int o = nb * 64 + tx * 4 + c;
                float bias = b2[o];
                float s = 0.f;
                #pragma unroll
                for (int r = 0; r < 4; r++) s += eluf(acc[q * 4 + r][c] + bias);
                float v = 0.25f * s;
                out[row * COUT + o] = v;
                __nv_bfloat16 h = __float2bfloat16(v);
                oh[row * KP1 + obase + o] = h;
                ol[row * KP1 + obase + o] = __float2bfloat16(v - __bfloat162float(h));
            }
        }
    }
}

// ---------------- final tiny GEMM ----------------
__global__ void final_kernel(const float* __restrict__ b3, float* __restrict__ out) {
    int warp = (blockIdx.x * blockDim.x + threadIdx.x) >> 5;
    int lane = threadIdx.x & 31;
    if (warp >= MTOT) return;
    const float* row = g_h2 + (size_t)warp * 256;
    float a0 = 0.f, a1 = 0.f;
    for (int k = lane; k < 256; k += 32) {
        float v = row[k];
        a0 = fmaf(v, g_W3p[k * 2 + 0], a0);
        a1 = fmaf(v, g_W3p[k * 2 + 1], a1);
    }
    #pragma unroll
    for (int off = 16; off; off >>= 1) {
        a0 += __shfl_down_sync(0xFFFFFFFFu, a0, off);
        a1 += __shfl_down_sync(0xFFFFFFFFu, a1, off);
    }
    if (lane == 0) {
        out[(size_t)warp * 2 + 0] = a0 + b3[0];
        out[(size_t)warp * 2 + 1] = a1 + b3[1];
    }
}

// ---------------- launch ----------------
extern "C" void kernel_launch(void* const* d_in, const int* in_sizes, int n_in,
                              void* d_out, int out_size) {
    const float* coords = (const float*)d_in[0];
    const float* feats  = (const float*)d_in[1];
    const float* c1w1 = (const float*)d_in[2];  const float* c1b1 = (const float*)d_in[3];
    const float* c1w2 = (const float*)d_in[4];  const float* c1b2 = (const float*)d_in[5];
    const float* c2w1 = (const float*)d_in[6];  const float* c2b1 = (const float*)d_in[7];
    const float* c2w2 = (const float*)d_in[8];  const float* c2b2 = (const float*)d_in[9];
    const float* c3w1 = (const float*)d_in[10]; const float* c3b1 = (const float*)d_in[11];
    const float* c3w2 = (const float*)d_in[12]; const float* c3b2 = (const float*)d_in[13];
    const float* ow1  = (const float*)d_in[14]; const float* ob1  = (const float*)d_in[15];
    const float* ow2  = (const float*)d_in[16]; const float* ob2  = (const float*)d_in[17];
    const float* ow3  = (const float*)d_in[18]; const float* ob3  = (const float*)d_in[19];
    float* out = (float*)d_out;

    float *out1p, *out2p, *Up, *Vp, *UVp, *h2p, *b1pp, *b2pp, *W3pp, *sb1p;
    __nv_bfloat16 *A1hp, *A1lp, *h1hp, *h1lp, *Ehp, *Elp;
    __nv_bfloat16 *Bt1hp, *Bt1lp, *Bt2hp, *Bt2lp, *Bc2hp, *Bc2lp, *Bc3hp, *Bc3lp, *Bs1hp, *Bs1lp;
    int* idxp;
    cudaGetSymbolAddress((void**)&out1p, g_out1);
    cudaGetSymbolAddress((void**)&out2p, g_out2);
    cudaGetSymbolAddress((void**)&Up,    g_U);
    cudaGetSymbolAddress((void**)&Vp,    g_V);
    cudaGetSymbolAddress((void**)&UVp,   g_UV);
    cudaGetSymbolAddress((void**)&idxp,  g_idx);
    cudaGetSymbolAddress((void**)&h2p,   g_h2);
    cudaGetSymbolAddress((void**)&b1pp,  g_b1p);
    cudaGetSymbolAddress((void**)&b2pp,  g_b2p);
    cudaGetSymbolAddress((void**)&W3pp,  g_W3p);
    cudaGetSymbolAddress((void**)&sb1p,  g_sb1);
    cudaGetSymbolAddress((void**)&A1hp,  g_A1h);
    cudaGetSymbolAddress((void**)&A1lp,  g_A1l);
    cudaGetSymbolAddress((void**)&h1hp,  g_h1h);
    cudaGetSymbolAddress((void**)&h1lp,  g_h1l);
    cudaGetSymbolAddress((void**)&Ehp,   g_Eh);
    cudaGetSymbolAddress((void**)&Elp,   g_El);
    cudaGetSymbolAddress((void**)&Bt1hp, g_Bt1h);
    cudaGetSymbolAddress((void**)&Bt1lp, g_Bt1l);
    cudaGetSymbolAddress((void**)&Bt2hp, g_Bt2h);
    cudaGetSymbolAddress((void**)&Bt2lp, g_Bt2l);
    cudaGetSymbolAddress((void**)&Bc2hp, g_Bc2h);
    cudaGetSymbolAddress((void**)&Bc2lp, g_Bc2l);
    cudaGetSymbolAddress((void**)&Bc3hp, g_Bc3h);
    cudaGetSymbolAddress((void**)&Bc3lp, g_Bc3l);
    cudaGetSymbolAddress((void**)&Bs1hp, g_Bs1h);
    cudaGetSymbolAddress((void**)&Bs1lp, g_Bs1l);

    const int sm_knn2   = (NN * 2 + NN) * 4;
    const int sm_knn64  = (NN * 64 + NN) * 4;
    const int sm_knn128 = (NN * 128 + NN) * 4;
    const int sm_s1_a = (5 * 132 + 2 * 16 * 64) * 4;
    const int sm_s1_b = (64 * 132 + 2 * 16 * 64) * 4;
    const int sm_s2_a = (32 * 132 + 16 * 64) * 4;
    const int sm_gemm = 2 * STG_BYTES + 512;   // 82432

    cudaFuncSetAttribute(knn_kernel<128>, cudaFuncAttributeMaxDynamicSharedMemorySize, sm_knn128);
    cudaFuncSetAttribute(gemm_mma,        cudaFuncAttributeMaxDynamicSharedMemorySize, sm_gemm);

    // weight prep
    pad_copy_kernel<<<2, 256>>>(b1pp, ob1, 1, 453, 1, 512);
    pad_copy_kernel<<<1, 256>>>(b2pp, ob2, 1, 226, 1, 256);
    pad_copy_kernel<<<2, 256>>>(W3pp, ow3, 226, 2, 256, 2);
    split_w1p_kernel<<<240, 256>>>(ow1, Bt1hp, Bt1lp);
    split_w_kernel<<<128, 256>>>(ow2, 453, 226, Bt2hp, Bt2lp, 256, KP2);
    split_w_kernel<<<16, 256>>>(c2w2, 96, 128, Bc2hp, Bc2lp, 128, 96);
    split_w_kernel<<<48, 256>>>(c3w2, 192, 256, Bc3hp, Bc3lp, 256, 192);
    split_s1w_kernel<<<48, 256>>>(c3w1, c3b1, Bs1hp, Bs1lp, sb1p);
    hcat_edges_kernel<<<4096, 256>>>(feats);

    // ---- edgeconv 1 (fp32: tiny) ----
    knn_kernel<2><<<BB, 128, sm_knn2>>>(coords, idxp);
    stage1_kernel<5, 32><<<BB, 256, sm_s1_a>>>(feats, c1w1, c1b1, Up, Vp);
    stage2_kernel<32, 64><<<dim3(BB, 4), 256, sm_s2_a>>>(Up, Vp, idxp, c1w2, c1b2,
                                                         out1p, A1hp, A1lp, 8);

    // ---- edgeconv 2 ----
    knn_kernel<64><<<BB, 128, sm_knn64>>>(out1p, idxp);
    stage1_kernel<64, 96><<<BB, 256, sm_s1_b>>>(out1p, c2w1, c2b1, Up, Vp);
    edge_gather<96><<<4096, 256>>>(Up, Vp, 96, idxp, Ehp, Elp);
    gemm_mma<<<dim3(ME / 128, 1), 256, sm_gemm>>>(Ehp, Elp, 96, Bc2hp, Bc2lp, c2b2,
                                                  A1hp, A1lp, KP1, 72, out2p, 128, 96, 2);

    // ---- edgeconv 3 ----
    knn_kernel<128><<<BB, 128, sm_knn128>>>(out2p, idxp);
    gemm_mma<<<dim3(MTOT / 128, 3), 256, sm_gemm>>>(A1hp + 72, A1lp + 72, KP1,
                                                    Bs1hp, Bs1lp, sb1p,
                                                    nullptr, nullptr, 0, 0, UVp, 384, 128, 3);
    edge_gather<192><<<8192, 256>>>(UVp, UVp + 192, 384, idxp, Ehp, Elp);
    gemm_mma<<<dim3(ME / 128, 2), 256, sm_gemm>>>(Ehp, Elp, 192, Bc3hp, Bc3lp, c3b2,
                                                  A1hp, A1lp, KP1, 200, nullptr, 0, 192, 2);

    // ---- head ----
    gemm_mma<<<dim3(MTOT / 128, 4), 256, sm_gemm>>>(A1hp, A1lp, KP1, Bt1hp, Bt1lp, b1pp,
                                                    h1hp, h1lp, KP2, 0, nullptr, 0, KP1, 0);
    gemm_mma<<<dim3(MTOT / 128, 2), 256, sm_gemm>>>(h1hp, h1lp, KP2, Bt2hp, Bt2lp, b2pp,
                                                    nullptr, nullptr, 0, 0, h2p, 256, KP2, 1);
    final_kernel<<<MTOT / 8, 256>>>(ob3, out);
}

// round 7
// speedup vs baseline: 1.2884x; 1.0333x over previous
#include <cuda_runtime.h>
#include <cuda_bf16.h>
#include <math.h>
#include <stdint.h>

#define BB 1024
#define NN 128
#define KK 4
#define MTOT (BB*NN)     // 131072
#define ME  (MTOT*KK)    // 524288 edges
#define KP1 480          // hcat padded K (head GEMM1)
#define KP2 512          // head GEMM2 K

// ---------------- scratch (device globals: allocation-free) ----------------
__device__ float g_out1[MTOT*64];
__device__ float g_out2[MTOT*128];
__device__ float g_U[MTOT*96];
__device__ float g_V[MTOT*96];
__device__ __align__(16) float g_UV[(size_t)MTOT*384];  // [U|V] for ec2 (96+96) / ec3 (192+192)
__device__ int   g_idx[MTOT*KK];
__device__ float g_h2[(size_t)MTOT*256];
__device__ float g_b1p[512];
__device__ float g_b2p[256];
__device__ float g_W3p[256*2];
__device__ float g_sb1[384];
__device__ float g_sb2[256];

// bf16 split operands (16B aligned)
// hcat cols: [0..5)=feats [5..8)=0 [8..72)=out1 [72..200)=out2 [200..456)=out3 [456..480)=0
__device__ __align__(16) __nv_bfloat16 g_A1h[(size_t)MTOT*KP1];
__device__ __align__(16) __nv_bfloat16 g_A1l[(size_t)MTOT*KP1];
__device__ __align__(16) __nv_bfloat16 g_h1h[(size_t)MTOT*KP2];
__device__ __align__(16) __nv_bfloat16 g_h1l[(size_t)MTOT*KP2];
__device__ __align__(16) __nv_bfloat16 g_Eh[(size_t)ME*192];
__device__ __align__(16) __nv_bfloat16 g_El[(size_t)ME*192];
__device__ __align__(16) __nv_bfloat16 g_Bt1h[512*KP1];
__device__ __align__(16) __nv_bfloat16 g_Bt1l[512*KP1];
__device__ __align__(16) __nv_bfloat16 g_Bt2h[256*KP2];
__device__ __align__(16) __nv_bfloat16 g_Bt2l[256*KP2];
__device__ __align__(16) __nv_bfloat16 g_Bc2h[128*96];
__device__ __align__(16) __nv_bfloat16 g_Bc2l[128*96];
__device__ __align__(16) __nv_bfloat16 g_Bc3h[256*192];
__device__ __align__(16) __nv_bfloat16 g_Bc3l[256*192];
__device__ __align__(16) __nv_bfloat16 g_Bs1h[384*128];
__device__ __align__(16) __nv_bfloat16 g_Bs1l[384*128];
__device__ __align__(16) __nv_bfloat16 g_Bs2h[256*64];
__device__ __align__(16) __nv_bfloat16 g_Bs2l[256*64];

__device__ __forceinline__ float eluf(float x) { return x > 0.f ? x : expm1f(x); }

__device__ __forceinline__ uint32_t smem_u32(const void* p) {
    uint32_t a;
    asm("{ .reg .u64 t; cvta.to.shared.u64 t, %1; cvt.u32.u64 %0, t; }" : "=r"(a) : "l"(p));
    return a;
}
__device__ __forceinline__ void cp16(uint32_t dst, const void* src) {
    asm volatile("cp.async.cg.shared.global [%0], [%1], 16;" :: "r"(dst), "l"(src));
}
#define CP_COMMIT() asm volatile("cp.async.commit_group;" ::: "memory")
#define CP_WAIT(n)  asm volatile("cp.async.wait_group %0;" :: "n"(n) : "memory")

#define LDSM_X4(r0, r1, r2, r3, addr) \
    asm volatile("ldmatrix.sync.aligned.m8n8.x4.shared.b16 {%0,%1,%2,%3}, [%4];" \
        : "=r"(r0), "=r"(r1), "=r"(r2), "=r"(r3) : "r"(addr))
#define LDSM_X2(r0, r1, addr) \
    asm volatile("ldmatrix.sync.aligned.m8n8.x2.shared.b16 {%0,%1}, [%2];" \
        : "=r"(r0), "=r"(r1) : "r"(addr))

#define MMA16816(d, a0, a1, a2, a3, b0, b1) \
    asm volatile("mma.sync.aligned.m16n8k16.row.col.f32.bf16.bf16.f32 " \
        "{%0,%1,%2,%3}, {%4,%5,%6,%7}, {%8,%9}, {%0,%1,%2,%3};" \
        : "+f"((d)[0]), "+f"((d)[1]), "+f"((d)[2]), "+f"((d)[3]) \
        : "r"(a0), "r"(a1), "r"(a2), "r"(a3), "r"(b0), "r"(b1))

#define STG_BYTES 40960
#define ROWB 80

// ---------------- weight prep ----------------
__global__ void pad_copy_kernel(float* __restrict__ dst, const float* __restrict__ src,
                                int sr, int sc, int dr, int dc) {
    int tot = dr * dc;
    for (int i = blockIdx.x * blockDim.x + threadIdx.x; i < tot; i += gridDim.x * blockDim.x) {
        int r = i / dc, c = i % dc;
        dst[i] = (r < sr && c < sc) ? src[r * sc + c] : 0.f;
    }
}

__global__ void split_w_kernel(const float* __restrict__ W, int sr, int sc,
                               __nv_bfloat16* __restrict__ oh, __nv_bfloat16* __restrict__ ol,
                               int Np, int Kp) {
    int tot = Np * Kp;
    for (int i = blockIdx.x * blockDim.x + threadIdx.x; i < tot; i += gridDim.x * blockDim.x) {
        int n = i / Kp, k = i % Kp;
        float v = (k < sr && n < sc) ? W[k * sc + n] : 0.f;
        __nv_bfloat16 h = __float2bfloat16(v);
        oh[i] = h;
        ol[i] = __float2bfloat16(v - __bfloat162float(h));
    }
}

// head GEMM1 weight with hcat-permuted K rows: [512][KP1]
__global__ void split_w1p_kernel(const float* __restrict__ W,
                                 __nv_bfloat16* __restrict__ oh, __nv_bfloat16* __restrict__ ol) {
    int tot = 512 * KP1;
    for (int i = blockIdx.x * blockDim.x + threadIdx.x; i < tot; i += gridDim.x * blockDim.x) {
        int n = i / KP1, k = i % KP1;
        int src = -1;
        if (k < 5)                    src = k;
        else if (k >= 8 && k < 72)    src = 5 + (k - 8);
        else if (k >= 72 && k < 200)  src = 69 + (k - 72);
        else if (k >= 200 && k < 456) src = 197 + (k - 200);
        float v = (src >= 0 && n < 453) ? W[(size_t)src * 453 + n] : 0.f;
        __nv_bfloat16 h = __float2bfloat16(v);
        oh[i] = h;
        ol[i] = __float2bfloat16(v - __bfloat162float(h));
    }
}

// generic stage1 combined weight: [Npad][C]; rows 0..H-1 = W1b^T, H..2H-1 = (W1a-W1b)^T; bias [0|b1|0]
// w1: [2C][H] row-major
__global__ void split_s1w_kernel(const float* __restrict__ w1, const float* __restrict__ b1,
                                 int C, int H, int Npad,
                                 __nv_bfloat16* __restrict__ oh, __nv_bfloat16* __restrict__ ol,
                                 float* __restrict__ biasv) {
    int tot = Npad * C;
    int t0 = blockIdx.x * blockDim.x + threadIdx.x;
    for (int i = t0; i < tot; i += gridDim.x * blockDim.x) {
        int n = i / C, k = i % C;
        float v = 0.f;
        if (n < H)           v = w1[(size_t)(C + k) * H + n];
        else if (n < 2 * H)  v = w1[(size_t)k * H + (n - H)] - w1[(size_t)(C + k) * H + (n - H)];
        __nv_bfloat16 h = __float2bfloat16(v);
        oh[i] = h;
        ol[i] = __float2bfloat16(v - __bfloat162float(h));
    }
    if (t0 < Npad) biasv[t0] = (t0 >= H && t0 < 2 * H) ? b1[t0 - H] : 0.f;
}

// fill hcat edge cols: 0..8 (feats+pad) and 456..480 (pad)
__global__ void hcat_edges_kernel(const float* __restrict__ feats) {
    size_t total = (size_t)MTOT * 32;
    for (size_t i = (size_t)blockIdx.x * blockDim.x + threadIdx.x; i < total;
         i += (size_t)gridDim.x * blockDim.x) {
        size_t m = i >> 5;
        int cq = (int)(i & 31);
        int c = (cq < 8) ? cq : 448 + cq;
        float v = (c < 5) ? feats[m * 5 + c] : 0.f;
        __nv_bfloat16 h = __float2bfloat16(v);
        g_A1h[m * KP1 + c] = h;
        g_A1l[m * KP1 + c] = __float2bfloat16(v - __bfloat162float(h));
    }
}

// ---------------- edge gather: E[e][c] = elu(V[p][c] + U[j][c]) -> bf16 split ----------------
template<int H>
__global__ void edge_gather(const float* __restrict__ Ub, const float* __restrict__ Vb,
                            int suv, const int* __restrict__ idx,
                            __nv_bfloat16* __restrict__ Eh, __nv_bfloat16* __restrict__ El) {
    const int GP = H / 8;
    size_t total = (size_t)ME * GP;
    for (size_t i = (size_t)blockIdx.x * blockDim.x + threadIdx.x; i < total;
         i += (size_t)gridDim.x * blockDim.x) {
        size_t e = i / GP;
        int g = (int)(i - e * GP);
        int p = (int)(e >> 2);
        int j = idx[e];
        int jg = (p & ~127) + j;
        const float4* vp = (const float4*)(Vb + (size_t)p * suv + g * 8);
        const float4* up = (const float4*)(Ub + (size_t)jg * suv + g * 8);
        float4 v0 = vp[0], v1 = vp[1], u0 = up[0], u1 = up[1];
        float r[8] = {v0.x+u0.x, v0.y+u0.y, v0.z+u0.z, v0.w+u0.w,
                      v1.x+u1.x, v1.y+u1.y, v1.z+u1.z, v1.w+u1.w};
        __nv_bfloat16 hh[8], ll[8];
        #pragma unroll
        for (int q = 0; q < 8; q++) {
            float vv = eluf(r[q]);
            hh[q] = __float2bfloat16(vv);
            ll[q] = __float2bfloat16(vv - __bfloat162float(hh[q]));
        }
        *(uint4*)&Eh[e * H + g * 8] = *(uint4*)hh;
        *(uint4*)&El[e * H + g * 8] = *(uint4*)ll;
    }
}

// ================= bf16x3-split tensor-core GEMM (mma.sync) =================
// out = post(A[M x Kdim(lda)] @ B^T[N x Kdim] + bias), via ah*bh + ah*bl + al*bh.
// mode 0: elu + bf16-split (oh/ol at ldoh, obase). mode 1: elu + fp32 (of). mode 3: plain fp32.
// mode 2: per-edge elu then mean over 4 rows -> fp32 of (opt) + bf16 split oh/ol (at ldoh, obase).
__global__ void __launch_bounds__(256) gemm_mma(
    const __nv_bfloat16* __restrict__ Ah, const __nv_bfloat16* __restrict__ Al, int lda,
    const __nv_bfloat16* __restrict__ Bh, const __nv_bfloat16* __restrict__ Bl,
    const float* __restrict__ bias,
    __nv_bfloat16* __restrict__ oh, __nv_bfloat16* __restrict__ ol, int ldoh, int obase,
    float* __restrict__ of, int ldof, int Kdim, int mode) {
    extern __shared__ char smem[];
    float* sbias = (float*)(smem + 2 * STG_BYTES);

    const int tid = threadIdx.x;
    const int warp = tid >> 5, lane = tid & 31;
    const size_t m0 = (size_t)blockIdx.x * 128;
    const int n0 = blockIdx.y * 128;
    const uint32_t sb = smem_u32(smem);

    if (tid < 128) sbias[tid] = bias[n0 + tid];

    auto issue = [&](int st, int k0) {
        uint32_t base = sb + st * STG_BYTES;
        #pragma unroll
        for (int i = tid; i < 2048; i += 256) {
            int mat = i >> 9, j = i & 511, r = j >> 2, c = j & 3;
            uint32_t daddr = base + mat * 10240 + r * ROWB + c * 16;
            const __nv_bfloat16* g;
            if (mat == 0)      g = &Ah[(m0 + r) * lda + k0 + c * 8];
            else if (mat == 1) g = &Al[(m0 + r) * lda + k0 + c * 8];
            else if (mat == 2) g = &Bh[(size_t)(n0 + r) * Kdim + k0 + c * 8];
            else               g = &Bl[(size_t)(n0 + r) * Kdim + k0 + c * 8];
            cp16(daddr, g);
        }
        CP_COMMIT();
    };

    const int wm = warp & 1, wn = warp >> 1;
    const int mbase = wm * 64, nbase = wn * 32;

    float acc[4][4][4];
    #pragma unroll
    for (int mi = 0; mi < 4; mi++)
        #pragma unroll
        for (int ni = 0; ni < 4; ni++)
            #pragma unroll
            for (int q = 0; q < 4; q++) acc[mi][ni][q] = 0.f;

    const int lr = lane & 7, seg = lane >> 3;
    const int arow = mbase + (seg & 1) * 8 + lr;
    const int acolq = (seg >> 1) * 8;
    const int brow = nbase + lr;
    const int bcolq = (seg & 1) * 8;

    issue(0, 0);

    const int NSTEP = Kdim >> 5;
    #pragma unroll 1
    for (int s = 0; s < NSTEP; s++) {
        if (s + 1 < NSTEP) { issue((s + 1) & 1, (s + 1) * 32); CP_WAIT(1); }
        else               { CP_WAIT(0); }
        __syncthreads();
        uint32_t base = sb + (s & 1) * STG_BYTES;
        uint32_t bAh = base, bAl = base + 10240, bBh = base + 20480, bBl = base + 30720;

        #pragma unroll
        for (int ks = 0; ks < 2; ks++) {
            int acol = ks * 16 + acolq;
            int bcol = ks * 16 + bcolq;
            uint32_t ah[4][4], al_[4][4], bh[4][2], bl[4][2];
            #pragma unroll
            for (int mi = 0; mi < 4; mi++) {
                LDSM_X4(ah[mi][0], ah[mi][1], ah[mi][2], ah[mi][3],
                        bAh + (arow + mi * 16) * ROWB + acol * 2);
                LDSM_X4(al_[mi][0], al_[mi][1], al_[mi][2], al_[mi][3],
                        bAl + (arow + mi * 16) * ROWB + acol * 2);
            }
            #pragma unroll
            for (int ni = 0; ni < 4; ni++) {
                LDSM_X2(bh[ni][0], bh[ni][1], bBh + (brow + ni * 8) * ROWB + bcol * 2);
                LDSM_X2(bl[ni][0], bl[ni][1], bBl + (brow + ni * 8) * ROWB + bcol * 2);
            }
            #pragma unroll
            for (int mi = 0; mi < 4; mi++)
                #pragma unroll
                for (int ni = 0; ni < 4; ni++) {
                    MMA16816(acc[mi][ni], ah[mi][0], ah[mi][1], ah[mi][2], ah[mi][3],
                             bh[ni][0], bh[ni][1]);
                    MMA16816(acc[mi][ni], ah[mi][0], ah[mi][1], ah[mi][2], ah[mi][3],
                             bl[ni][0], bl[ni][1]);
                    MMA16816(acc[mi][ni], al_[mi][0], al_[mi][1], al_[mi][2], al_[mi][3],
                             bh[ni][0], bh[ni][1]);
                }
        }
        __syncthreads();
    }

    const int gq = lane >> 2, tq = lane & 3;

    if (mode == 2) {
        float* stg = (float*)smem;
        #pragma unroll
        for (int mi = 0; mi < 4; mi++)
            #pragma unroll
            for (int ni = 0; ni < 4; ni++)
                #pragma unroll
                for (int half = 0; half < 2; half++) {
                    int ml = mbase + mi * 16 + gq + half * 8;
                    int nl = nbase + ni * 8 + tq * 2;
                    stg[ml * 132 + nl]     = eluf(acc[mi][ni][half * 2 + 0] + sbias[nl]);
                    stg[ml * 132 + nl + 1] = eluf(acc[mi][ni][half * 2 + 1] + sbias[nl + 1]);
                }
        __syncthreads();
        for (int i = tid; i < 32 * 128; i += 256) {
            int pl = i >> 7, c = i & 127;
            float s4 = stg[(pl * 4 + 0) * 132 + c] + stg[(pl * 4 + 1) * 132 + c]
                     + stg[(pl * 4 + 2) * 132 + c] + stg[(pl * 4 + 3) * 132 + c];
            float v = 0.25f * s4;
            size_t pm = (m0 >> 2) + pl;
            if (of) of[pm * (size_t)ldof + n0 + c] = v;
            __nv_bfloat16 h = __float2bfloat16(v);
            size_t o = pm * (size_t)ldoh + obase + n0 + c;
            oh[o] = h;
            ol[o] = __float2bfloat16(v - __bfloat162float(h));
        }
        return;
    }

    const bool doelu = (mode != 3);
    #pragma unroll
    for (int mi = 0; mi < 4; mi++) {
        #pragma unroll
        for (int ni = 0; ni < 4; ni++) {
            #pragma unroll
            for (int half = 0; half < 2; half++) {
                size_t m = m0 + mbase + mi * 16 + gq + half * 8;
                int nl = nbase + ni * 8 + tq * 2;
                float v0 = acc[mi][ni][half * 2 + 0] + sbias[nl];
                float v1 = acc[mi][ni][half * 2 + 1] + sbias[nl + 1];
                if (doelu) { v0 = eluf(v0); v1 = eluf(v1); }
                if (mode == 0) {
                    size_t o = m * (size_t)ldoh + obase + n0 + nl;
                    __nv_bfloat162 hv, lv;
                    hv.x = __float2bfloat16(v0);
                    hv.y = __float2bfloat16(v1);
                    lv.x = __float2bfloat16(v0 - __bfloat162float(hv.x));
                    lv.y = __float2bfloat16(v1 - __bfloat162float(hv.y));
                    *(__nv_bfloat162*)&oh[o] = hv;
                    *(__nv_bfloat162*)&ol[o] = lv;
                } else {
                    *(float2*)&of[m * (size_t)ldof + n0 + nl] = make_float2(v0, v1);
                }
            }
        }
    }
}

// ---------------- KNN ----------------
template<int C>
__global__ void __launch_bounds__(128) knn_kernel(const float* __restrict__ x,
                                                  int* __restrict__ out_idx) {
    extern __shared__ float sm[];
    float* sx = sm;
    float* sn = sm + NN * C;
    int b = blockIdx.x, t = threadIdx.x;
    const float* xb = x + (size_t)b * NN * C;
    for (int i = t; i < NN * C; i += 128) sx[i] = xb[i];
    __syncthreads();
    float nrm = 0.f;
    float rx[C];
    #pragma unroll
    for (int c = 0; c < C; c++) { rx[c] = sx[t * C + c]; nrm += rx[c] * rx[c]; }
    sn[t] = nrm;
    __syncthreads();

    float bd0 = 3e38f, bd1 = 3e38f, bd2 = 3e38f, bd3 = 3e38f;
    int   bi0 = 0, bi1 = 0, bi2 = 0, bi3 = 0;
    for (int j = 0; j < NN; j++) {
        float dot = 0.f;
        if (C % 4 == 0) {
            #pragma unroll
            for (int c = 0; c < C; c += 4) {
                float4 v = *reinterpret_cast<const float4*>(&sx[j * C + c]);
                dot += rx[c] * v.x + rx[c+1] * v.y + rx[c+2] * v.z + rx[c+3] * v.w;
            }
        } else {
            #pragma unroll
            for (int c = 0; c < C; c++) dot += rx[c] * sx[j * C + c];
        }
        float d = nrm + sn[j] - 2.f * dot;
        if (j == t) d += 1e9f;
        if (d < bd3) {
            if (d < bd0)      { bd3=bd2;bi3=bi2; bd2=bd1;bi2=bi1; bd1=bd0;bi1=bi0; bd0=d;bi0=j; }
            else if (d < bd1) { bd3=bd2;bi3=bi2; bd2=bd1;bi2=bi1; bd1=d;bi1=j; }
            else if (d < bd2) { bd3=bd2;bi3=bi2; bd2=d;bi2=j; }
            else              { bd3=d;bi3=j; }
        }
    }
    int* o = out_idx + ((size_t)b * NN + t) * KK;
    o[0] = bi0; o[1] = bi1; o[2] = bi2; o[3] = bi3;
}

// ---------------- EdgeConv stage 1 (fp32, ec1 only): U = X@W1b ; V = X@W1a - U + b1 ----------------
template<int C, int H>
__global__ void __launch_bounds__(256) stage1_kernel(const float* __restrict__ x,
                                                     const float* __restrict__ w1,
                                                     const float* __restrict__ b1,
                                                     float* __restrict__ U,
                                                     float* __restrict__ V) {
    const int XS = 132;
    extern __shared__ float sm[];
    float* XT = sm;
    float* Ba = sm + C * XS;
    float* Bb = Ba + 16 * 64;
    int b = blockIdx.x;
    int tid = threadIdx.x;
    int tx = tid & 15, ty = tid >> 4;
    const float* xb = x + (size_t)b * NN * C;
    for (int i = tid; i < NN * C; i += 256) {
        int p = i / C, c = i % C;
        XT[c * XS + p] = xb[i];
    }
    __syncthreads();

    const int NBT = (H + 63) / 64;
    for (int nb = 0; nb < NBT; nb++) {
        float au[8][4], aw[8][4];
        #pragma unroll
        for (int r = 0; r < 8; r++)
            #pragma unroll
            for (int c = 0; c < 4; c++) { au[r][c] = 0.f; aw[r][c] = 0.f; }

        for (int c0 = 0; c0 < C; c0 += 16) {
            int kc = (C - c0 < 16) ? (C - c0) : 16;
            __syncthreads();
            for (int li = tid; li < 16 * 64; li += 256) {
                int kk = li >> 6, n = li & 63;
                int h = nb * 64 + n;
                float va = 0.f, vb = 0.f;
                if (kk < kc && h < H) {
                    va = w1[(size_t)(c0 + kk) * H + h];
                    vb = w1[(size_t)(C + c0 + kk) * H + h];
                }
                Ba[kk * 64 + n] = va;
                Bb[kk * 64 + n] = vb;
            }
            __syncthreads();
            for (int kk = 0; kk < kc; kk++) {
                float4 a0 = *reinterpret_cast<float4*>(&XT[(c0 + kk) * XS + ty * 8]);
                float4 a1 = *reinterpret_cast<float4*>(&XT[(c0 + kk) * XS + ty * 8 + 4]);
                float4 va = *reinterpret_cast<float4*>(&Ba[kk * 64 + tx * 4]);
                float4 vb = *reinterpret_cast<float4*>(&Bb[kk * 64 + tx * 4]);
                float a[8]  = {a0.x, a0.y, a0.z, a0.w, a1.x, a1.y, a1.z, a1.w};
                float wa[4] = {va.x, va.y, va.z, va.w};
                float wb[4] = {vb.x, vb.y, vb.z, vb.w};
                #pragma unroll
                for (int r = 0; r < 8; r++)
                    #pragma unroll
                    for (int c = 0; c < 4; c++) {
                        au[r][c] = fmaf(a[r], wb[c], au[r][c]);
                        aw[r][c] = fmaf(a[r], wa[c], aw[r][c]);
                    }
            }
        }
        #pragma unroll
        for (int r = 0; r < 8; r++) {
            int p = ty * 8 + r;
            size_t base = ((size_t)b * NN + p) * H;
            #pragma unroll
            for (int c = 0; c < 4; c++) {
                int h = nb * 64 + tx * 4 + c;
                if (h < H) {
                    float u = au[r][c];
                    U[base + h] = u;
                    V[base + h] = aw[r][c] - u + b1[h];
                }
            }
        }
    }
}

// ---------------- EdgeConv stage 2 fp32 (ec1 only) + hcat split write ----------------
template<int H, int COUT>
__global__ void __launch_bounds__(256) stage2_kernel(const float* __restrict__ U,
                                                     const float* __restrict__ V,
                                                     const int* __restrict__ idx,
                                                     const float* __restrict__ w2,
                                                     const float* __restrict__ b2,
                                                     float* __restrict__ out,
                                                     __nv_bfloat16* __restrict__ oh,
                                                     __nv_bfloat16* __restrict__ ol,
                                                     int obase) {
    const int ES = 132;
    extern __shared__ float sm[];
    float* M1 = sm;
    float* Bs = sm + H * ES;
    int b = blockIdx.x, pt = blockIdx.y;
    int tid = threadIdx.x;
    int tx = tid & 15, ty = tid >> 4;
    int p0 = pt * 32;

    {
        int e = tid & 127, s = tid >> 7;
        int pl = e >> 2, kk = e & 3;
        int p = p0 + pl;
        int j = idx[((size_t)b * NN + p) * KK + kk];
        const float* vp = V + ((size_t)b * NN + p) * H;
        const float* up = U + ((size_t)b * NN + j) * H;
        int h0 = s * (H / 2), h1 = h0 + H / 2;
        for (int h = h0; h < h1; h++)
            M1[h * ES + e] = eluf(vp[h] + up[h]);
    }
    __syncthreads();

    const int NBT = COUT / 64;
    for (int nb = 0; nb < NBT; nb++) {
        float acc[8][4];
        #pragma unroll
        for (int r = 0; r < 8; r++)
            #pragma unroll
            for (int c = 0; c < 4; c++) acc[r][c] = 0.f;

        for (int k0 = 0; k0 < H; k0 += 16) {
            __syncthreads();
            {
                int kk = tid >> 4, nq = tid & 15;
                *reinterpret_cast<float4*>(&Bs[kk * 64 + nq * 4]) =
                    *reinterpret_cast<const float4*>(&w2[(size_t)(k0 + kk) * COUT + nb * 64 + nq * 4]);
            }
            __syncthreads();
            #pragma unroll
            for (int kk = 0; kk < 16; kk++) {
                float4 a0 = *reinterpret_cast<float4*>(&M1[(k0 + kk) * ES + ty * 8]);
                float4 a1 = *reinterpret_cast<float4*>(&M1[(k0 + kk) * ES + ty * 8 + 4]);
                float4 b4 = *reinterpret_cast<float4*>(&Bs[kk * 64 + tx * 4]);
                float a[8]  = {a0.x, a0.y, a0.z, a0.w, a1.x, a1.y, a1.z, a1.w};
                float wv[4] = {b4.x, b4.y, b4.z, b4.w};
                #pragma unroll
                for (int r = 0; r < 8; r++)
                    #pragma unroll
                    for (int c = 0; c < 4; c++)
                        acc[r][c] = fmaf(a[r], wv[c], acc[r][c]);
            }
        }
        #pragma unroll
        for (int q = 0; q < 2; q++) {
            int p = p0 + ty * 2 + q;
            size_t row = (size_t)b * NN + p;
            #pragma unroll
            for (int c = 0; c < 4; c++) {
                int o = nb * 64 + tx * 4 + c;
                float bias = b2[o];
                float s = 0.f;
                #pragma unroll
                for (int r = 0; r < 4; r++) s += eluf(acc[q * 4 + r][c] + bias);
                float v = 0.25f * s;
                out[row * COUT + o] = v;
                __nv_bfloat16 h = __float2bfloat16(v);
                oh[row * KP1 + obase + o] = h;
                ol[row * KP1 + obase + o] = __float2bfloat16(v - __bfloat162float(h));
            }
        }
    }
}

// ---------------- final tiny GEMM ----------------
__global__ void final_kernel(const float* __restrict__ b3, float* __restrict__ out) {
    int warp = (blockIdx.x * blockDim.x + threadIdx.x) >> 5;
    int lane = threadIdx.x & 31;
    if (warp >= MTOT) return;
    const float* row = g_h2 + (size_t)warp * 256;
    float a0 = 0.f, a1 = 0.f;
    for (int k = lane; k < 256; k += 32) {
        float v = row[k];
        a0 = fmaf(v, g_W3p[k * 2 + 0], a0);
        a1 = fmaf(v, g_W3p[k * 2 + 1], a1);
    }
    #pragma unroll
    for (int off = 16; off; off >>= 1) {
        a0 += __shfl_down_sync(0xFFFFFFFFu, a0, off);
        a1 += __shfl_down_sync(0xFFFFFFFFu, a1, off);
    }
    if (lane == 0) {
        out[(size_t)warp * 2 + 0] = a0 + b3[0];
        out[(size_t)warp * 2 + 1] = a1 + b3[1];
    }
}

// ---------------- launch ----------------
extern "C" void kernel_launch(void* const* d_in, const int* in_sizes, int n_in,
                              void* d_out, int out_size) {
    const float* coords = (const float*)d_in[0];
    const float* feats  = (const float*)d_in[1];
    const float* c1w1 = (const float*)d_in[2];  const float* c1b1 = (const float*)d_in[3];
    const float* c1w2 = (const float*)d_in[4];  const float* c1b2 = (const float*)d_in[5];
    const float* c2w1 = (const float*)d_in[6];  const float* c2b1 = (const float*)d_in[7];
    const float* c2w2 = (const float*)d_in[8];  const float* c2b2 = (const float*)d_in[9];
    const float* c3w1 = (const float*)d_in[10]; const float* c3b1 = (const float*)d_in[11];
    const float* c3w2 = (const float*)d_in[12]; const float* c3b2 = (const float*)d_in[13];
    const float* ow1  = (const float*)d_in[14]; const float* ob1  = (const float*)d_in[15];
    const float* ow2  = (const float*)d_in[16]; const float* ob2  = (const float*)d_in[17];
    const float* ow3  = (const float*)d_in[18]; const float* ob3  = (const float*)d_in[19];
    float* out = (float*)d_out;

    float *out1p, *out2p, *Up, *Vp, *UVp, *h2p, *b1pp, *b2pp, *W3pp, *sb1p, *sb2p;
    __nv_bfloat16 *A1hp, *A1lp, *h1hp, *h1lp, *Ehp, *Elp;
    __nv_bfloat16 *Bt1hp, *Bt1lp, *Bt2hp, *Bt2lp, *Bc2hp, *Bc2lp, *Bc3hp, *Bc3lp;
    __nv_bfloat16 *Bs1hp, *Bs1lp, *Bs2hp, *Bs2lp;
    int* idxp;
    cudaGetSymbolAddress((void**)&out1p, g_out1);
    cudaGetSymbolAddress((void**)&out2p, g_out2);
    cudaGetSymbolAddress((void**)&Up,    g_U);
    cudaGetSymbolAddress((void**)&Vp,    g_V);
    cudaGetSymbolAddress((void**)&UVp,   g_UV);
    cudaGetSymbolAddress((void**)&idxp,  g_idx);
    cudaGetSymbolAddress((void**)&h2p,   g_h2);
    cudaGetSymbolAddress((void**)&b1pp,  g_b1p);
    cudaGetSymbolAddress((void**)&b2pp,  g_b2p);
    cudaGetSymbolAddress((void**)&W3pp,  g_W3p);
    cudaGetSymbolAddress((void**)&sb1p,  g_sb1);
    cudaGetSymbolAddress((void**)&sb2p,  g_sb2);
    cudaGetSymbolAddress((void**)&A1hp,  g_A1h);
    cudaGetSymbolAddress((void**)&A1lp,  g_A1l);
    cudaGetSymbolAddress((void**)&h1hp,  g_h1h);
    cudaGetSymbolAddress((void**)&h1lp,  g_h1l);
    cudaGetSymbolAddress((void**)&Ehp,   g_Eh);
    cudaGetSymbolAddress((void**)&Elp,   g_El);
    cudaGetSymbolAddress((void**)&Bt1hp, g_Bt1h);
    cudaGetSymbolAddress((void**)&Bt1lp, g_Bt1l);
    cudaGetSymbolAddress((void**)&Bt2hp, g_Bt2h);
    cudaGetSymbolAddress((void**)&Bt2lp, g_Bt2l);
    cudaGetSymbolAddress((void**)&Bc2hp, g_Bc2h);
    cudaGetSymbolAddress((void**)&Bc2lp, g_Bc2l);
    cudaGetSymbolAddress((void**)&Bc3hp, g_Bc3h);
    cudaGetSymbolAddress((void**)&Bc3lp, g_Bc3l);
    cudaGetSymbolAddress((void**)&Bs1hp, g_Bs1h);
    cudaGetSymbolAddress((void**)&Bs1lp, g_Bs1l);
    cudaGetSymbolAddress((void**)&Bs2hp, g_Bs2h);
    cudaGetSymbolAddress((void**)&Bs2lp, g_Bs2l);

    const int sm_knn2   = (NN * 2 + NN) * 4;
    const int sm_knn64  = (NN * 64 + NN) * 4;
    const int sm_knn128 = (NN * 128 + NN) * 4;
    const int sm_s1_a = (5 * 132 + 2 * 16 * 64) * 4;
    const int sm_s2_a = (32 * 132 + 16 * 64) * 4;
    const int sm_gemm = 2 * STG_BYTES + 512;   // 82432

    cudaFuncSetAttribute(knn_kernel<128>, cudaFuncAttributeMaxDynamicSharedMemorySize, sm_knn128);
    cudaFuncSetAttribute(gemm_mma,        cudaFuncAttributeMaxDynamicSharedMemorySize, sm_gemm);

    // weight prep
    pad_copy_kernel<<<2, 256>>>(b1pp, ob1, 1, 453, 1, 512);
    pad_copy_kernel<<<1, 256>>>(b2pp, ob2, 1, 226, 1, 256);
    pad_copy_kernel<<<2, 256>>>(W3pp, ow3, 226, 2, 256, 2);
    split_w1p_kernel<<<240, 256>>>(ow1, Bt1hp, Bt1lp);
    split_w_kernel<<<128, 256>>>(ow2, 453, 226, Bt2hp, Bt2lp, 256, KP2);
    split_w_kernel<<<16, 256>>>(c2w2, 96, 128, Bc2hp, Bc2lp, 128, 96);
    split_w_kernel<<<48, 256>>>(c3w2, 192, 256, Bc3hp, Bc3lp, 256, 192);
    split_s1w_kernel<<<48, 256>>>(c3w1, c3b1, 128, 192, 384, Bs1hp, Bs1lp, sb1p);
    split_s1w_kernel<<<16, 256>>>(c2w1, c2b1, 64, 96, 256, Bs2hp, Bs2lp, sb2p);
    hcat_edges_kernel<<<4096, 256>>>(feats);

    // ---- edgeconv 1 (fp32: tiny) ----
    knn_kernel<2><<<BB, 128, sm_knn2>>>(coords, idxp);
    stage1_kernel<5, 32><<<BB, 256, sm_s1_a>>>(feats, c1w1, c1b1, Up, Vp);
    stage2_kernel<32, 64><<<dim3(BB, 4), 256, sm_s2_a>>>(Up, Vp, idxp, c1w2, c1b2,
                                                         out1p, A1hp, A1lp, 8);

    // ---- edgeconv 2 ----
    knn_kernel<64><<<BB, 128, sm_knn64>>>(out1p, idxp);
    // stage1-ec2 on tensor cores: [U(96)|V(96)|pad] = out1 @ Bs2^T + sb2  (A = hcat out1 slice)
    gemm_mma<<<dim3(MTOT / 128, 2), 256, sm_gemm>>>(A1hp + 8, A1lp + 8, KP1,
                                                    Bs2hp, Bs2lp, sb2p,
                                                    nullptr, nullptr, 0, 0, UVp, 384, 64, 3);
    edge_gather<96><<<4096, 256>>>(UVp, UVp + 96, 384, idxp, Ehp, Elp);
    gemm_mma<<<dim3(ME / 128, 1), 256, sm_gemm>>>(Ehp, Elp, 96, Bc2hp, Bc2lp, c2b2,
                                                  A1hp, A1lp, KP1, 72, out2p, 128, 96, 2);

    // ---- edgeconv 3 ----
    knn_kernel<128><<<BB, 128, sm_knn128>>>(out2p, idxp);
    gemm_mma<<<dim3(MTOT / 128, 3), 256, sm_gemm>>>(A1hp + 72, A1lp + 72, KP1,
                                                    Bs1hp, Bs1lp, sb1p,
                                                    nullptr, nullptr, 0, 0, UVp, 384, 128, 3);
    edge_gather<192><<<8192, 256>>>(UVp, UVp + 192, 384, idxp, Ehp, Elp);
    gemm_mma<<<dim3(ME / 128, 2), 256, sm_gemm>>>(Ehp, Elp, 192, Bc3hp, Bc3lp, c3b2,
                                                  A1hp, A1lp, KP1, 200, nullptr, 0, 192, 2);

    // ---- head ----
    gemm_mma<<<dim3(MTOT / 128, 4), 256, sm_gemm>>>(A1hp, A1lp, KP1, Bt1hp, Bt1lp, b1pp,
                                                    h1hp, h1lp, KP2, 0, nullptr, 0, KP1, 0);
    gemm_mma<<<dim3(MTOT / 128, 2), 256, sm_gemm>>>(h1hp, h1lp, KP2, Bt2hp, Bt2lp, b2pp,
                                                    nullptr, nullptr, 0, 0, h2p, 256, KP2, 1);
    final_kernel<<<MTOT / 8, 256>>>(ob3, out);
}